// round 5
// baseline (speedup 1.0000x reference)
#include <cuda_runtime.h>

#define BG 4
#define NN 8192
#define EG 65536
#define F0 128
#define F1 256
#define F2 1024
#define NOUTD 18
#define MTOT (BG*NN)   // 32768 rows total across graphs

// ---------------- scratch (static device globals; referenced directly from device code) ----------------
__device__ __align__(16) float g_deg [BG*NN];
__device__ __align__(16) float g_dinv[BG*NN];
__device__ __align__(16) float g_agg1[(size_t)MTOT*F0];
__device__ __align__(16) float g_h1  [(size_t)MTOT*F1];
__device__ __align__(16) float g_agg2[(size_t)MTOT*F1];
__device__ __align__(16) float g_h2  [(size_t)MTOT*F2];
__device__ __align__(16) float g_Wc  [F2*32];
__device__ __align__(16) float g_bc  [32];

// ---------------- degree / dinv ----------------
__global__ void deg_init_k() {
    int i = blockIdx.x*blockDim.x + threadIdx.x;
    g_deg[i] = 1.0f;   // self-loop contributes 1 to every node's degree
}

__global__ void deg_count_k(const int* __restrict__ edges) {
    int i = blockIdx.x*blockDim.x + threadIdx.x;       // over BG*EG
    int b = i >> 16;                                   // EG = 65536
    int e = i & (EG-1);
    int dst = edges[(size_t)b*2*EG + EG + e] & (NN-1);
    atomicAdd(&g_deg[b*NN + dst], 1.0f);
}

__global__ void dinv_k() {
    int i = blockIdx.x*blockDim.x + threadIdx.x;
    g_dinv[i] = rsqrtf(g_deg[i]);                      // deg >= 1 always (self-loop)
}

// ---------------- aggregation: agg = dinv^2 * X (self-loop term) then scatter edges ----------------
template<int F>
__device__ __forceinline__ void agg_init_body(const float* __restrict__ X, float* __restrict__ agg) {
    size_t i = (size_t)blockIdx.x*blockDim.x + threadIdx.x;   // over MTOT*F/4
    int node = (int)(i / (F/4));
    float s = g_dinv[node]; s = s*s;
    float4 v = ((const float4*)X)[i];
    v.x *= s; v.y *= s; v.z *= s; v.w *= s;
    ((float4*)agg)[i] = v;
}

__global__ void agg1_init_k(const float* __restrict__ nodes) { agg_init_body<F0>(nodes, g_agg1); }
__global__ void agg2_init_k()                                { agg_init_body<F1>(g_h1,  g_agg2); }

template<int F>
__device__ __forceinline__ void scatter_body(const int* __restrict__ edges,
                                             const float* __restrict__ X,
                                             float* __restrict__ agg) {
    int w    = blockIdx.x*8 + (threadIdx.x >> 5);      // warp per edge, 8 warps/block
    int lane = threadIdx.x & 31;
    int b = w >> 16;                                   // w in [0, BG*EG)
    int e = w & (EG-1);
    const int* eb = edges + (size_t)b*2*EG;
    int src = eb[e]      & (NN-1);
    int dst = eb[EG + e] & (NN-1);
    float nrm = g_dinv[b*NN + src] * g_dinv[b*NN + dst];
    const float* xs = X   + ((size_t)b*NN + src) * F;
    float*       ad = agg + ((size_t)b*NN + dst) * F;
#pragma unroll
    for (int c = 0; c < F/128; c++) {
        int f = c*128 + lane*4;
        float4 v = *(const float4*)(xs + f);
        atomicAdd(ad + f + 0, v.x * nrm);
        atomicAdd(ad + f + 1, v.y * nrm);
        atomicAdd(ad + f + 2, v.z * nrm);
        atomicAdd(ad + f + 3, v.w * nrm);
    }
}

__global__ void scatter1_k(const int* __restrict__ edges,
                           const float* __restrict__ nodes) { scatter_body<F0>(edges, nodes, g_agg1); }
__global__ void scatter2_k(const int* __restrict__ edges) { scatter_body<F1>(edges, g_h1, g_agg2); }

// ---------------- SGEMM: C = epi(A[MxK] @ B[KxN] + bias) ----------------
// EPI=0: relu -> C.  EPI=1: head split-write (cols 0..17 -> logits, col 18 -> values).
template<int M, int N, int K, int BM, int BN, int BK, int TM, int TN, int EPI>
__device__ __forceinline__ void sgemm_body(const float* __restrict__ A,
                                           const float* __restrict__ Bm,
                                           const float* __restrict__ bias,
                                           float* __restrict__ C,
                                           float* __restrict__ C2) {
    __shared__ float As[BK][BM+4];
    __shared__ float Bs[BK][BN+4];
    constexpr int NTX = BN/TN;           // threads along N
    constexpr int NTY = BM/TM;           // threads along M
    constexpr int T   = NTX*NTY;         // 256
    const int tid = threadIdx.x;
    const int tx = tid % NTX, ty = tid / NTX;
    const int bM = blockIdx.y * BM;
    const int bN = blockIdx.x * BN;

    float acc[TM][TN];
#pragma unroll
    for (int i = 0; i < TM; i++)
#pragma unroll
        for (int j = 0; j < TN; j++) acc[i][j] = 0.f;

    for (int kb = 0; kb < K; kb += BK) {
        // A tile (transposed into As[k][m]); BM*BK/4 float4 loads
#pragma unroll
        for (int i = tid; i < BM*BK/4; i += T) {
            int m  = i / (BK/4);
            int kq = i % (BK/4);
            float4 v = *(const float4*)(A + (size_t)(bM+m)*K + kb + kq*4);
            As[kq*4+0][m] = v.x; As[kq*4+1][m] = v.y;
            As[kq*4+2][m] = v.z; As[kq*4+3][m] = v.w;
        }
        // B tile
#pragma unroll
        for (int i = tid; i < BK*BN/4; i += T) {
            int k  = i / (BN/4);
            int nq = i % (BN/4);
            *(float4*)(&Bs[k][nq*4]) = *(const float4*)(Bm + (size_t)(kb+k)*N + bN + nq*4);
        }
        __syncthreads();
#pragma unroll
        for (int k = 0; k < BK; k++) {
            float ra[TM], rb[TN];
#pragma unroll
            for (int i = 0; i < TM; i++) ra[i] = As[k][ty*TM + i];
#pragma unroll
            for (int j = 0; j < TN; j++) rb[j] = Bs[k][tx*TN + j];
#pragma unroll
            for (int i = 0; i < TM; i++)
#pragma unroll
                for (int j = 0; j < TN; j++)
                    acc[i][j] += ra[i] * rb[j];
        }
        __syncthreads();
    }

    if (EPI == 0) {
#pragma unroll
        for (int i = 0; i < TM; i++) {
            int row = bM + ty*TM + i;
#pragma unroll
            for (int j = 0; j < TN; j += 4) {
                int col = bN + tx*TN + j;
                float4 v;
                v.x = fmaxf(acc[i][j+0] + bias[col+0], 0.f);
                v.y = fmaxf(acc[i][j+1] + bias[col+1], 0.f);
                v.z = fmaxf(acc[i][j+2] + bias[col+2], 0.f);
                v.w = fmaxf(acc[i][j+3] + bias[col+3], 0.f);
                *(float4*)(C + (size_t)row*N + col) = v;
            }
        }
    } else {
#pragma unroll
        for (int i = 0; i < TM; i++) {
            int row = bM + ty*TM + i;
#pragma unroll
            for (int j = 0; j < TN; j++) {
                int col = bN + tx*TN + j;
                float v = acc[i][j] + bias[col];
                if (col < NOUTD)       C [(size_t)row*NOUTD + col] = v;   // logits
                else if (col == NOUTD) C2[row] = v;                       // values
            }
        }
    }
}

__global__ void __launch_bounds__(256) gemm1_k(const float* __restrict__ W0,
                                               const float* __restrict__ b0) {
    sgemm_body<MTOT, F1, F0, 128,128,16, 8,8, 0>(g_agg1, W0, b0, g_h1, nullptr);
}

__global__ void __launch_bounds__(256) gemm2_k(const float* __restrict__ W1,
                                               const float* __restrict__ b1) {
    sgemm_body<MTOT, F2, F1, 128,128,16, 8,8, 0>(g_agg2, W1, b1, g_h2, nullptr);
}

__global__ void __launch_bounds__(256) head_k(float* __restrict__ logits,
                                              float* __restrict__ values) {
    sgemm_body<MTOT, 32, F2, 128,32,16, 8,2, 1>(g_h2, g_Wc, g_bc, logits, values);
}

// ---------------- pack W_logit + W_val into [K,32] padded matrix ----------------
__global__ void pack_k(const float* __restrict__ Wl, const float* __restrict__ bl,
                       const float* __restrict__ Wv, const float* __restrict__ bv) {
    int t = blockIdx.x*blockDim.x + threadIdx.x;   // F2*32
    int k = t >> 5, j = t & 31;
    float v = 0.f;
    if (j < NOUTD)       v = Wl[k*NOUTD + j];
    else if (j == NOUTD) v = Wv[k];
    g_Wc[t] = v;
    if (t < 32) {
        float b = 0.f;
        if (t < NOUTD)       b = bl[t];
        else if (t == NOUTD) b = bv[0];
        g_bc[t] = b;
    }
}

// ---------------- launch (pure kernel launches; inputs resolved by size signature) ----------------
extern "C" void kernel_launch(void* const* d_in, const int* in_sizes, int n_in,
                              void* d_out, int out_size) {
    // Two possible orderings of the 10 inputs:
    //  insertion: nodes, edges, W0, b0, W1, b1, W_logit, b_logit, W_val, b_val
    //  sorted:    W0, W1, W_logit, W_val, b0, b1, b_logit, b_val, edges, nodes
    // Detect via in_sizes[0]: nodes = 4194304 elems (insertion), W0 = 32768 elems (sorted).
    int iNodes, iEdges, iW0, ib0, iW1, ib1, iWl, ibl, iWv, ibv;
    if (n_in >= 10 && in_sizes[0] == BG*NN*F0) {          // insertion order
        iNodes=0; iEdges=1; iW0=2; ib0=3; iW1=4; ib1=5; iWl=6; ibl=7; iWv=8; ibv=9;
    } else {                                               // sorted-key order
        iW0=0; iW1=1; iWl=2; iWv=3; ib0=4; ib1=5; ibl=6; ibv=7; iEdges=8; iNodes=9;
    }
    const float* nodes = (const float*)d_in[iNodes];
    const int*   edges = (const int*)  d_in[iEdges];   // int64 in reference -> int32 without x64
    const float* W0 = (const float*)d_in[iW0];
    const float* b0 = (const float*)d_in[ib0];
    const float* W1 = (const float*)d_in[iW1];
    const float* b1 = (const float*)d_in[ib1];
    const float* Wl = (const float*)d_in[iWl];
    const float* bl = (const float*)d_in[ibl];
    const float* Wv = (const float*)d_in[iWv];
    const float* bv = (const float*)d_in[ibv];
    float* outp   = (float*)d_out;
    float* logits = outp;
    float* values = outp + (size_t)MTOT*NOUTD;

    // degrees + normalization
    deg_init_k <<<MTOT/256, 256>>>();
    deg_count_k<<<BG*EG/256, 256>>>(edges);
    dinv_k     <<<MTOT/256, 256>>>();

    // layer 1: aggregate X (128-d) then GEMM -> relu
    agg1_init_k<<<MTOT*(F0/4)/256, 256>>>(nodes);
    scatter1_k <<<BG*EG/8, 256>>>(edges, nodes);
    gemm1_k    <<<dim3(F1/128, MTOT/128), 256>>>(W0, b0);

    // layer 2: aggregate h1 (256-d) then GEMM -> relu
    agg2_init_k<<<MTOT*(F1/4)/256, 256>>>();
    scatter2_k <<<BG*EG/8, 256>>>(edges);
    gemm2_k    <<<dim3(F2/128, MTOT/128), 256>>>(W1, b1);

    // heads: pack [1024,19]->[1024,32], one skinny GEMM with split-write epilogue
    pack_k<<<F2*32/256, 256>>>(Wl, bl, Wv, bv);
    head_k<<<dim3(1, MTOT/128), 256>>>(logits, values);
}

// round 6
// speedup vs baseline: 1.0048x; 1.0048x over previous
#include <cuda_runtime.h>

#define BG 4
#define NN 8192
#define EG 65536
#define F0 128
#define F1 256
#define F2 1024
#define NOUTD 18
#define MTOT (BG*NN)   // 32768 rows total across graphs

// ---------------- scratch (static device globals; referenced directly from device code) ----------------
__device__ __align__(16) float g_deg [BG*NN];
__device__ __align__(16) float g_dinv[BG*NN];
__device__ __align__(16) float g_agg1[(size_t)MTOT*F0];
__device__ __align__(16) float g_h1  [(size_t)MTOT*F1];
__device__ __align__(16) float g_agg2[(size_t)MTOT*F1];
__device__ __align__(16) float g_h2  [(size_t)MTOT*F2];
__device__ __align__(16) float g_Wc  [F2*32];
__device__ __align__(16) float g_bc  [32];

// ---------------- packed f32x2 helpers ----------------
__device__ __forceinline__ unsigned long long pack2(float lo, float hi) {
    unsigned long long r;
    asm("mov.b64 %0, {%1, %2};" : "=l"(r) : "f"(lo), "f"(hi));
    return r;
}
__device__ __forceinline__ void unpack2(unsigned long long v, float& lo, float& hi) {
    asm("mov.b64 {%0, %1}, %2;" : "=f"(lo), "=f"(hi) : "l"(v));
}
__device__ __forceinline__ void fma2(unsigned long long& d, unsigned long long a,
                                     unsigned long long b, unsigned long long c) {
    asm("fma.rn.f32x2 %0, %1, %2, %3;" : "=l"(d) : "l"(a), "l"(b), "l"(c));
}

// ---------------- degree / dinv ----------------
__global__ void deg_init_k() {
    int i = blockIdx.x*blockDim.x + threadIdx.x;
    g_deg[i] = 1.0f;   // self-loop contributes 1 to every node's degree
}

__global__ void deg_count_k(const int* __restrict__ edges) {
    int i = blockIdx.x*blockDim.x + threadIdx.x;       // over BG*EG
    int b = i >> 16;                                   // EG = 65536
    int e = i & (EG-1);
    int dst = edges[(size_t)b*2*EG + EG + e] & (NN-1);
    atomicAdd(&g_deg[b*NN + dst], 1.0f);
}

__global__ void dinv_k() {
    int i = blockIdx.x*blockDim.x + threadIdx.x;
    g_dinv[i] = rsqrtf(g_deg[i]);                      // deg >= 1 always (self-loop)
}

// ---------------- aggregation: agg = dinv^2 * X (self-loop term) then scatter edges ----------------
template<int F>
__device__ __forceinline__ void agg_init_body(const float* __restrict__ X, float* __restrict__ agg) {
    size_t i = (size_t)blockIdx.x*blockDim.x + threadIdx.x;   // over MTOT*F/4
    int node = (int)(i / (F/4));
    float s = g_dinv[node]; s = s*s;
    float4 v = ((const float4*)X)[i];
    v.x *= s; v.y *= s; v.z *= s; v.w *= s;
    ((float4*)agg)[i] = v;
}

__global__ void agg1_init_k(const float* __restrict__ nodes) { agg_init_body<F0>(nodes, g_agg1); }
__global__ void agg2_init_k()                                { agg_init_body<F1>(g_h1,  g_agg2); }

template<int F>
__device__ __forceinline__ void scatter_body(const int* __restrict__ edges,
                                             const float* __restrict__ X,
                                             float* __restrict__ agg) {
    int w    = blockIdx.x*8 + (threadIdx.x >> 5);      // warp per edge, 8 warps/block
    int lane = threadIdx.x & 31;
    int b = w >> 16;                                   // w in [0, BG*EG)
    int e = w & (EG-1);
    const int* eb = edges + (size_t)b*2*EG;
    int src = eb[e]      & (NN-1);
    int dst = eb[EG + e] & (NN-1);
    float nrm = g_dinv[b*NN + src] * g_dinv[b*NN + dst];
    const float* xs = X   + ((size_t)b*NN + src) * F;
    float*       ad = agg + ((size_t)b*NN + dst) * F;
#pragma unroll
    for (int c = 0; c < F/128; c++) {
        int f = c*128 + lane*4;
        float4 v = *(const float4*)(xs + f);
        atomicAdd(ad + f + 0, v.x * nrm);
        atomicAdd(ad + f + 1, v.y * nrm);
        atomicAdd(ad + f + 2, v.z * nrm);
        atomicAdd(ad + f + 3, v.w * nrm);
    }
}

__global__ void scatter1_k(const int* __restrict__ edges,
                           const float* __restrict__ nodes) { scatter_body<F0>(edges, nodes, g_agg1); }
__global__ void scatter2_k(const int* __restrict__ edges) { scatter_body<F1>(edges, g_h1, g_agg2); }

// ---------------- SGEMM (f32x2 microkernel): C = epi(A[MxK] @ B[KxN] + bias) ----------------
// EPI=0: relu -> C.  EPI=1: head split-write (cols 0..17 -> logits, col 18 -> values).
template<int M, int N, int K, int BM, int BN, int BK, int TM, int TN, int EPI>
__device__ __forceinline__ void sgemm_body(const float* __restrict__ A,
                                           const float* __restrict__ Bm,
                                           const float* __restrict__ bias,
                                           float* __restrict__ C,
                                           float* __restrict__ C2) {
    __shared__ float As[BK][BM+4];
    __shared__ __align__(8) float Bs[BK][BN+4];
    constexpr int NTX = BN/TN;           // threads along N
    constexpr int NTY = BM/TM;           // threads along M
    constexpr int T   = NTX*NTY;         // 256
    constexpr int TN2 = TN/2;
    const int tid = threadIdx.x;
    const int tx = tid % NTX, ty = tid / NTX;
    const int bM = blockIdx.y * BM;
    const int bN = blockIdx.x * BN;

    unsigned long long acc[TM][TN2];
#pragma unroll
    for (int i = 0; i < TM; i++)
#pragma unroll
        for (int j = 0; j < TN2; j++) acc[i][j] = 0ull;

    for (int kb = 0; kb < K; kb += BK) {
        // A tile (transposed into As[k][m]); BM*BK/4 float4 loads
#pragma unroll
        for (int i = tid; i < BM*BK/4; i += T) {
            int m  = i / (BK/4);
            int kq = i % (BK/4);
            float4 v = *(const float4*)(A + (size_t)(bM+m)*K + kb + kq*4);
            As[kq*4+0][m] = v.x; As[kq*4+1][m] = v.y;
            As[kq*4+2][m] = v.z; As[kq*4+3][m] = v.w;
        }
        // B tile
#pragma unroll
        for (int i = tid; i < BK*BN/4; i += T) {
            int k  = i / (BN/4);
            int nq = i % (BN/4);
            *(float4*)(&Bs[k][nq*4]) = *(const float4*)(Bm + (size_t)(kb+k)*N + bN + nq*4);
        }
        __syncthreads();
#pragma unroll
        for (int k = 0; k < BK; k++) {
            unsigned long long ra2[TM], rb2[TN2];
#pragma unroll
            for (int i = 0; i < TM; i++) {
                float a = As[k][ty*TM + i];
                ra2[i] = pack2(a, a);
            }
#pragma unroll
            for (int j = 0; j < TN2; j++) {
                float2 b2 = *(const float2*)(&Bs[k][tx*TN + j*2]);
                rb2[j] = pack2(b2.x, b2.y);
            }
#pragma unroll
            for (int i = 0; i < TM; i++)
#pragma unroll
                for (int j = 0; j < TN2; j++)
                    fma2(acc[i][j], ra2[i], rb2[j], acc[i][j]);
        }
        __syncthreads();
    }

    if (EPI == 0) {
#pragma unroll
        for (int i = 0; i < TM; i++) {
            int row = bM + ty*TM + i;
#pragma unroll
            for (int j = 0; j < TN2; j += 2) {
                int col = bN + tx*TN + j*2;
                float a0,a1,a2,a3;
                unpack2(acc[i][j],   a0, a1);
                unpack2(acc[i][j+1], a2, a3);
                float4 v;
                v.x = fmaxf(a0 + bias[col+0], 0.f);
                v.y = fmaxf(a1 + bias[col+1], 0.f);
                v.z = fmaxf(a2 + bias[col+2], 0.f);
                v.w = fmaxf(a3 + bias[col+3], 0.f);
                *(float4*)(C + (size_t)row*N + col) = v;
            }
        }
    } else {
#pragma unroll
        for (int i = 0; i < TM; i++) {
            int row = bM + ty*TM + i;
#pragma unroll
            for (int j = 0; j < TN2; j++) {
                int col = bN + tx*TN + j*2;
                float a0, a1;
                unpack2(acc[i][j], a0, a1);
                float v0 = a0 + bias[col+0];
                float v1 = a1 + bias[col+1];
                if (col   < NOUTD)       C [(size_t)row*NOUTD + col  ] = v0;
                else if (col   == NOUTD) C2[row] = v0;
                if (col+1 < NOUTD)       C [(size_t)row*NOUTD + col+1] = v1;
                else if (col+1 == NOUTD) C2[row] = v1;
            }
        }
    }
}

__global__ void __launch_bounds__(256) gemm1_k(const float* __restrict__ W0,
                                               const float* __restrict__ b0) {
    sgemm_body<MTOT, F1, F0, 128,128,16, 8,8, 0>(g_agg1, W0, b0, g_h1, nullptr);
}

__global__ void __launch_bounds__(256) gemm2_k(const float* __restrict__ W1,
                                               const float* __restrict__ b1) {
    sgemm_body<MTOT, F2, F1, 128,128,16, 8,8, 0>(g_agg2, W1, b1, g_h2, nullptr);
}

__global__ void __launch_bounds__(256) head_k(float* __restrict__ logits,
                                              float* __restrict__ values) {
    sgemm_body<MTOT, 32, F2, 128,32,16, 8,2, 1>(g_h2, g_Wc, g_bc, logits, values);
}

// ---------------- pack W_logit + W_val into [K,32] padded matrix ----------------
__global__ void pack_k(const float* __restrict__ Wl, const float* __restrict__ bl,
                       const float* __restrict__ Wv, const float* __restrict__ bv) {
    int t = blockIdx.x*blockDim.x + threadIdx.x;   // F2*32
    int k = t >> 5, j = t & 31;
    float v = 0.f;
    if (j < NOUTD)       v = Wl[k*NOUTD + j];
    else if (j == NOUTD) v = Wv[k];
    g_Wc[t] = v;
    if (t < 32) {
        float b = 0.f;
        if (t < NOUTD)       b = bl[t];
        else if (t == NOUTD) b = bv[0];
        g_bc[t] = b;
    }
}

// ---------------- launch (pure kernel launches; inputs resolved by size signature) ----------------
extern "C" void kernel_launch(void* const* d_in, const int* in_sizes, int n_in,
                              void* d_out, int out_size) {
    int iNodes, iEdges, iW0, ib0, iW1, ib1, iWl, ibl, iWv, ibv;
    if (n_in >= 10 && in_sizes[0] == BG*NN*F0) {          // insertion order
        iNodes=0; iEdges=1; iW0=2; ib0=3; iW1=4; ib1=5; iWl=6; ibl=7; iWv=8; ibv=9;
    } else {                                               // sorted-key order
        iW0=0; iW1=1; iWl=2; iWv=3; ib0=4; ib1=5; ibl=6; ibv=7; iEdges=8; iNodes=9;
    }
    const float* nodes = (const float*)d_in[iNodes];
    const int*   edges = (const int*)  d_in[iEdges];
    const float* W0 = (const float*)d_in[iW0];
    const float* b0 = (const float*)d_in[ib0];
    const float* W1 = (const float*)d_in[iW1];
    const float* b1 = (const float*)d_in[ib1];
    const float* Wl = (const float*)d_in[iWl];
    const float* bl = (const float*)d_in[ibl];
    const float* Wv = (const float*)d_in[iWv];
    const float* bv = (const float*)d_in[ibv];
    float* outp   = (float*)d_out;
    float* logits = outp;
    float* values = outp + (size_t)MTOT*NOUTD;

    // degrees + normalization
    deg_init_k <<<MTOT/256, 256>>>();
    deg_count_k<<<BG*EG/256, 256>>>(edges);
    dinv_k     <<<MTOT/256, 256>>>();

    // layer 1: aggregate X (128-d) then GEMM -> relu
    agg1_init_k<<<MTOT*(F0/4)/256, 256>>>(nodes);
    scatter1_k <<<BG*EG/8, 256>>>(edges, nodes);
    gemm1_k    <<<dim3(F1/128, MTOT/128), 256>>>(W0, b0);

    // layer 2: aggregate h1 (256-d) then GEMM -> relu
    agg2_init_k<<<MTOT*(F1/4)/256, 256>>>();
    scatter2_k <<<BG*EG/8, 256>>>(edges);
    gemm2_k    <<<dim3(F2/128, MTOT/128), 256>>>(W1, b1);

    // heads: pack [1024,19]->[1024,32], one skinny GEMM with split-write epilogue
    pack_k<<<F2*32/256, 256>>>(Wl, bl, Wv, bv);
    head_k<<<dim3(1, MTOT/128), 256>>>(logits, values);
}

// round 9
// speedup vs baseline: 1.4896x; 1.4824x over previous
#include <cuda_runtime.h>
#include <cstdint>

#define BG 4
#define NN 8192
#define EG 65536
#define F0 128
#define F1 256
#define F2 1024
#define NOUTD 18
#define MTOT (BG*NN)   // 32768 rows total across graphs

// ---------------- scratch (static device globals; ONLY referenced from device code) ----------------
__device__ __align__(16) float g_deg [BG*NN];
__device__ __align__(16) float g_dinv[BG*NN];
__device__ __align__(16) float g_agg1[(size_t)MTOT*F0];
__device__ __align__(16) float g_h1  [(size_t)MTOT*F1];
__device__ __align__(16) float g_agg2[(size_t)MTOT*F1];
__device__ __align__(16) float g_h2  [(size_t)MTOT*F2];
__device__ __align__(16) float g_Wc  [F2*32];
__device__ __align__(16) float g_bc  [32];

// ---------------- small helpers ----------------
__device__ __forceinline__ uint32_t f2tf32(float x) {
    uint32_t r;
    asm("cvt.rn.tf32.f32 %0, %1;" : "=r"(r) : "f"(x));
    return r;
}
__device__ __forceinline__ void mma_tf32(float c[4], const uint32_t a[4], const uint32_t b[2]) {
    asm("mma.sync.aligned.m16n8k8.row.col.f32.tf32.tf32.f32 "
        "{%0,%1,%2,%3}, {%4,%5,%6,%7}, {%8,%9}, {%0,%1,%2,%3};"
        : "+f"(c[0]), "+f"(c[1]), "+f"(c[2]), "+f"(c[3])
        : "r"(a[0]), "r"(a[1]), "r"(a[2]), "r"(a[3]), "r"(b[0]), "r"(b[1]));
}

// ---------------- degree / dinv ----------------
__global__ void deg_init_k() {
    int i = blockIdx.x*blockDim.x + threadIdx.x;
    g_deg[i] = 1.0f;
}

__global__ void deg_count_k(const int* __restrict__ edges) {
    int i = blockIdx.x*blockDim.x + threadIdx.x;       // over BG*EG
    int b = i >> 16;
    int e = i & (EG-1);
    int dst = edges[(size_t)b*2*EG + EG + e] & (NN-1);
    atomicAdd(&g_deg[b*NN + dst], 1.0f);
}

__global__ void dinv_k() {
    int i = blockIdx.x*blockDim.x + threadIdx.x;
    g_dinv[i] = rsqrtf(g_deg[i]);
}

// ---------------- aggregation ----------------
template<int F>
__device__ __forceinline__ void agg_init_body(const float* __restrict__ X, float* __restrict__ agg) {
    size_t i = (size_t)blockIdx.x*blockDim.x + threadIdx.x;
    int node = (int)(i / (F/4));
    float s = g_dinv[node]; s = s*s;
    float4 v = ((const float4*)X)[i];
    v.x *= s; v.y *= s; v.z *= s; v.w *= s;
    ((float4*)agg)[i] = v;
}

__global__ void agg1_init_k(const float* __restrict__ nodes) { agg_init_body<F0>(nodes, g_agg1); }
__global__ void agg2_init_k()                                { agg_init_body<F1>(g_h1,  g_agg2); }

template<int F>
__device__ __forceinline__ void scatter_body(const int* __restrict__ edges,
                                             const float* __restrict__ X,
                                             float* __restrict__ agg) {
    int w    = blockIdx.x*8 + (threadIdx.x >> 5);
    int lane = threadIdx.x & 31;
    int b = w >> 16;
    int e = w & (EG-1);
    const int* eb = edges + (size_t)b*2*EG;
    int src = eb[e]      & (NN-1);
    int dst = eb[EG + e] & (NN-1);
    float nrm = g_dinv[b*NN + src] * g_dinv[b*NN + dst];
    const float* xs = X   + ((size_t)b*NN + src) * F;
    float*       ad = agg + ((size_t)b*NN + dst) * F;
#pragma unroll
    for (int c = 0; c < F/128; c++) {
        int f = c*128 + lane*4;
        float4 v = *(const float4*)(xs + f);
        atomicAdd(ad + f + 0, v.x * nrm);
        atomicAdd(ad + f + 1, v.y * nrm);
        atomicAdd(ad + f + 2, v.z * nrm);
        atomicAdd(ad + f + 3, v.w * nrm);
    }
}

__global__ void scatter1_k(const int* __restrict__ edges,
                           const float* __restrict__ nodes) { scatter_body<F0>(edges, nodes, g_agg1); }
__global__ void scatter2_k(const int* __restrict__ edges) { scatter_body<F1>(edges, g_h1, g_agg2); }

// ---------------- tf32 tensor-core GEMM body: C = relu(A[MxK] @ B[KxN] + bias) ----------------
// CTA tile 128x128x32, 8 warps in 2(M)x4(N), warp tile 64x32, m16n8k8 fragments.
template<int N, int K>
__device__ __forceinline__ void mma_gemm_body(const float* __restrict__ A,
                                              const float* __restrict__ Bm,
                                              const float* __restrict__ bias,
                                              float* __restrict__ C) {
    __shared__ uint32_t As[128][36];    // [row][k] tf32, pad 36 -> frag LDS conflict-free
    __shared__ uint32_t Bs[32][136];    // [k][col] tf32, pad 136 -> frag LDS conflict-free

    const int tid  = threadIdx.x;
    const int warp = tid >> 5, lane = tid & 31;
    const int wm = warp & 1, wn = warp >> 1;   // 2x4 warp grid
    const int gid = lane >> 2, tig = lane & 3;
    const int bM = blockIdx.y * 128;
    const int bN = blockIdx.x * 128;

    float acc[4][4][4];
#pragma unroll
    for (int i = 0; i < 4; i++)
#pragma unroll
        for (int j = 0; j < 4; j++)
#pragma unroll
            for (int q = 0; q < 4; q++) acc[i][j][q] = 0.f;

    for (int kb = 0; kb < K; kb += 32) {
        // A tile: 128x32 floats = 1024 float4, 4 per thread
#pragma unroll
        for (int i = tid; i < 1024; i += 256) {
            int row = i >> 3;
            int c4  = (i & 7) * 4;
            float4 v = *(const float4*)(A + (size_t)(bM+row)*K + kb + c4);
            uint4 t = { f2tf32(v.x), f2tf32(v.y), f2tf32(v.z), f2tf32(v.w) };
            *(uint4*)(&As[row][c4]) = t;
        }
        // B tile: 32x128 floats = 1024 float4, 4 per thread
#pragma unroll
        for (int i = tid; i < 1024; i += 256) {
            int kr = i >> 5;
            int c4 = (i & 31) * 4;
            float4 v = *(const float4*)(Bm + (size_t)(kb+kr)*N + bN + c4);
            uint4 t = { f2tf32(v.x), f2tf32(v.y), f2tf32(v.z), f2tf32(v.w) };
            *(uint4*)(&Bs[kr][c4]) = t;
        }
        __syncthreads();

#pragma unroll
        for (int k8 = 0; k8 < 4; k8++) {
            const int kc = k8*8 + tig;
            uint32_t a[4][4], b[4][2];
#pragma unroll
            for (int mj = 0; mj < 4; mj++) {
                int r = wm*64 + mj*16 + gid;
                a[mj][0] = As[r  ][kc];
                a[mj][1] = As[r+8][kc];
                a[mj][2] = As[r  ][kc+4];
                a[mj][3] = As[r+8][kc+4];
            }
#pragma unroll
            for (int nj = 0; nj < 4; nj++) {
                int cN = wn*32 + nj*8 + gid;
                b[nj][0] = Bs[kc  ][cN];
                b[nj][1] = Bs[kc+4][cN];
            }
#pragma unroll
            for (int mj = 0; mj < 4; mj++)
#pragma unroll
                for (int nj = 0; nj < 4; nj++)
                    mma_tf32(acc[mj][nj], a[mj], b[nj]);
        }
        __syncthreads();
    }

    // epilogue: bias + relu, float2 stores (c0,c1 adjacent cols)
#pragma unroll
    for (int mj = 0; mj < 4; mj++) {
        int row0 = bM + wm*64 + mj*16 + gid;
#pragma unroll
        for (int nj = 0; nj < 4; nj++) {
            int col = bN + wn*32 + nj*8 + 2*tig;
            float bx = bias[col], by = bias[col+1];
            float2 v0 = { fmaxf(acc[mj][nj][0] + bx, 0.f), fmaxf(acc[mj][nj][1] + by, 0.f) };
            float2 v1 = { fmaxf(acc[mj][nj][2] + bx, 0.f), fmaxf(acc[mj][nj][3] + by, 0.f) };
            *(float2*)(C + (size_t)row0*N + col)     = v0;
            *(float2*)(C + (size_t)(row0+8)*N + col) = v1;
        }
    }
}

// device-side binding of scratch globals (host must never take their address)
__global__ void __launch_bounds__(256) gemm1_k(const float* __restrict__ W0,
                                               const float* __restrict__ b0) {
    mma_gemm_body<F1, F0>(g_agg1, W0, b0, g_h1);
}
__global__ void __launch_bounds__(256) gemm2_k(const float* __restrict__ W1,
                                               const float* __restrict__ b1) {
    mma_gemm_body<F2, F1>(g_agg2, W1, b1, g_h2);
}

// ---------------- fp32 f32x2 SGEMM for the head (split-write epilogue) ----------------
__device__ __forceinline__ unsigned long long pack2(float lo, float hi) {
    unsigned long long r;
    asm("mov.b64 %0, {%1, %2};" : "=l"(r) : "f"(lo), "f"(hi));
    return r;
}
__device__ __forceinline__ void unpack2(unsigned long long v, float& lo, float& hi) {
    asm("mov.b64 {%0, %1}, %2;" : "=f"(lo), "=f"(hi) : "l"(v));
}
__device__ __forceinline__ void fma2(unsigned long long& d, unsigned long long a,
                                     unsigned long long b, unsigned long long c) {
    asm("fma.rn.f32x2 %0, %1, %2, %3;" : "=l"(d) : "l"(a), "l"(b), "l"(c));
}

__global__ void __launch_bounds__(256) head_k(float* __restrict__ logits,
                                              float* __restrict__ values) {
    constexpr int Nn = 32, Kk = F2, BM = 128, BN = 32, BK = 16, TM = 8, TN = 2;
    __shared__ float As[BK][BM+4];
    __shared__ __align__(8) float Bs[BK][BN+4];
    constexpr int NTX = BN/TN, T = 256;
    constexpr int TN2 = TN/2;
    const int tid = threadIdx.x;
    const int tx = tid % NTX, ty = tid / NTX;
    const int bM = blockIdx.y * BM;

    unsigned long long acc[TM][TN2];
#pragma unroll
    for (int i = 0; i < TM; i++)
#pragma unroll
        for (int j = 0; j < TN2; j++) acc[i][j] = 0ull;

    for (int kb = 0; kb < Kk; kb += BK) {
#pragma unroll
        for (int i = tid; i < BM*BK/4; i += T) {
            int m  = i / (BK/4);
            int kq = i % (BK/4);
            float4 v = *(const float4*)(g_h2 + (size_t)(bM+m)*Kk + kb + kq*4);
            As[kq*4+0][m] = v.x; As[kq*4+1][m] = v.y;
            As[kq*4+2][m] = v.z; As[kq*4+3][m] = v.w;
        }
#pragma unroll
        for (int i = tid; i < BK*BN/4; i += T) {
            int k  = i / (BN/4);
            int nq = i % (BN/4);
            *(float4*)(&Bs[k][nq*4]) = *(const float4*)(g_Wc + (size_t)(kb+k)*Nn + nq*4);
        }
        __syncthreads();
#pragma unroll
        for (int k = 0; k < BK; k++) {
            unsigned long long ra2[TM], rb2[TN2];
#pragma unroll
            for (int i = 0; i < TM; i++) {
                float a = As[k][ty*TM + i];
                ra2[i] = pack2(a, a);
            }
#pragma unroll
            for (int j = 0; j < TN2; j++) {
                float2 b2 = *(const float2*)(&Bs[k][tx*TN + j*2]);
                rb2[j] = pack2(b2.x, b2.y);
            }
#pragma unroll
            for (int i = 0; i < TM; i++)
#pragma unroll
                for (int j = 0; j < TN2; j++)
                    fma2(acc[i][j], ra2[i], rb2[j], acc[i][j]);
        }
        __syncthreads();
    }

#pragma unroll
    for (int i = 0; i < TM; i++) {
        int row = bM + ty*TM + i;
#pragma unroll
        for (int j = 0; j < TN2; j++) {
            int col = tx*TN + j*2;
            float a0, a1;
            unpack2(acc[i][j], a0, a1);
            float v0 = a0 + g_bc[col+0];
            float v1 = a1 + g_bc[col+1];
            if (col   < NOUTD)       logits[(size_t)row*NOUTD + col  ] = v0;
            else if (col   == NOUTD) values[row] = v0;
            if (col+1 < NOUTD)       logits[(size_t)row*NOUTD + col+1] = v1;
            else if (col+1 == NOUTD) values[row] = v1;
        }
    }
}

// ---------------- pack W_logit + W_val into [K,32] padded matrix ----------------
__global__ void pack_k(const float* __restrict__ Wl, const float* __restrict__ bl,
                       const float* __restrict__ Wv, const float* __restrict__ bv) {
    int t = blockIdx.x*blockDim.x + threadIdx.x;   // F2*32
    int k = t >> 5, j = t & 31;
    float v = 0.f;
    if (j < NOUTD)       v = Wl[k*NOUTD + j];
    else if (j == NOUTD) v = Wv[k];
    g_Wc[t] = v;
    if (t < 32) {
        float b = 0.f;
        if (t < NOUTD)       b = bl[t];
        else if (t == NOUTD) b = bv[0];
        g_bc[t] = b;
    }
}

// ---------------- launch (pure kernel launches; only harness pointers passed as args) ----------------
extern "C" void kernel_launch(void* const* d_in, const int* in_sizes, int n_in,
                              void* d_out, int out_size) {
    int iNodes, iEdges, iW0, ib0, iW1, ib1, iWl, ibl, iWv, ibv;
    if (n_in >= 10 && in_sizes[0] == BG*NN*F0) {          // insertion order
        iNodes=0; iEdges=1; iW0=2; ib0=3; iW1=4; ib1=5; iWl=6; ibl=7; iWv=8; ibv=9;
    } else {                                               // sorted-key order
        iW0=0; iW1=1; iWl=2; iWv=3; ib0=4; ib1=5; ibl=6; ibv=7; iEdges=8; iNodes=9;
    }
    const float* nodes = (const float*)d_in[iNodes];
    const int*   edges = (const int*)  d_in[iEdges];
    const float* W0 = (const float*)d_in[iW0];
    const float* b0 = (const float*)d_in[ib0];
    const float* W1 = (const float*)d_in[iW1];
    const float* b1 = (const float*)d_in[ib1];
    const float* Wl = (const float*)d_in[iWl];
    const float* bl = (const float*)d_in[ibl];
    const float* Wv = (const float*)d_in[iWv];
    const float* bv = (const float*)d_in[ibv];
    float* outp   = (float*)d_out;
    float* logits = outp;
    float* values = outp + (size_t)MTOT*NOUTD;

    // degrees + normalization
    deg_init_k <<<MTOT/256, 256>>>();
    deg_count_k<<<BG*EG/256, 256>>>(edges);
    dinv_k     <<<MTOT/256, 256>>>();

    // layer 1: aggregate X (128-d) then tf32 GEMM -> relu
    agg1_init_k<<<MTOT*(F0/4)/256, 256>>>(nodes);
    scatter1_k <<<BG*EG/8, 256>>>(edges, nodes);
    gemm1_k    <<<dim3(F1/128, MTOT/128), 256>>>(W0, b0);

    // layer 2: aggregate h1 (256-d) then tf32 GEMM -> relu
    agg2_init_k<<<MTOT*(F1/4)/256, 256>>>();
    scatter2_k <<<BG*EG/8, 256>>>(edges);
    gemm2_k    <<<dim3(F2/128, MTOT/128), 256>>>(W1, b1);

    // heads: pack [1024,19]->[1024,32], fp32 skinny GEMM with split-write epilogue
    pack_k<<<F2*32/256, 256>>>(Wl, bl, Wv, bv);
    head_k<<<dim3(1, MTOT/128), 256>>>(logits, values);
}

// round 10
// speedup vs baseline: 2.0549x; 1.3795x over previous
#include <cuda_runtime.h>
#include <cstdint>

#define BG 4
#define NN 8192
#define EG 65536
#define F0 128
#define F1 256
#define F2 1024
#define NOUTD 18
#define MTOT (BG*NN)   // 32768 rows total across graphs

// ---------------- scratch (static device globals; ONLY referenced from device code) ----------------
__device__ __align__(16) float g_dinv[MTOT];
__device__ __align__(16) float g_agg1[(size_t)MTOT*F0];
__device__ __align__(16) float g_h1  [(size_t)MTOT*F1];
__device__ __align__(16) float g_agg2[(size_t)MTOT*F1];
__device__ __align__(16) float g_h2  [(size_t)MTOT*F2];
__device__ __align__(16) float g_Wc  [F2*32];
__device__ __align__(16) float g_bc  [32];
// CSR scratch
__device__ int g_cnt [MTOT];
__device__ int g_cur [MTOT];
__device__ int g_off [MTOT+1];
__device__ int g_csrc[BG*EG];

// ---------------- small helpers ----------------
__device__ __forceinline__ uint32_t f2tf32(float x) {
    uint32_t r;
    asm("cvt.rn.tf32.f32 %0, %1;" : "=r"(r) : "f"(x));
    return r;
}
__device__ __forceinline__ void mma_tf32(float c[4], const uint32_t a[4], const uint32_t b[2]) {
    asm("mma.sync.aligned.m16n8k8.row.col.f32.tf32.tf32.f32 "
        "{%0,%1,%2,%3}, {%4,%5,%6,%7}, {%8,%9}, {%0,%1,%2,%3};"
        : "+f"(c[0]), "+f"(c[1]), "+f"(c[2]), "+f"(c[3])
        : "r"(a[0]), "r"(a[1]), "r"(a[2]), "r"(a[3]), "r"(b[0]), "r"(b[1]));
}

// ---------------- CSR build ----------------
__global__ void zero_k() {
    int i = blockIdx.x*blockDim.x + threadIdx.x;
    g_cnt[i] = 0;
    g_cur[i] = 0;
}

__global__ void cnt_k(const int* __restrict__ edges) {
    int i = blockIdx.x*blockDim.x + threadIdx.x;       // over BG*EG
    int b = i >> 16;
    int e = i & (EG-1);
    int dst = edges[(size_t)b*2*EG + EG + e] & (NN-1);
    atomicAdd(&g_cnt[b*NN + dst], 1);
}

__global__ void dinv_k() {
    int i = blockIdx.x*blockDim.x + threadIdx.x;
    g_dinv[i] = rsqrtf(1.0f + (float)g_cnt[i]);        // +1 self-loop
}

// one block, 1024 threads, 32 entries each -> exclusive scan of g_cnt into g_off
__global__ void __launch_bounds__(1024) scan_k() {
    __shared__ int part[1024];
    int t = threadIdx.x;
    int base = t*32;
    int loc[32];
    int s = 0;
#pragma unroll
    for (int i = 0; i < 32; i++) { loc[i] = s; s += g_cnt[base+i]; }
    part[t] = s;
    __syncthreads();
    for (int d = 1; d < 1024; d <<= 1) {
        int v = (t >= d) ? part[t-d] : 0;
        __syncthreads();
        part[t] += v;
        __syncthreads();
    }
    int excl = (t == 0) ? 0 : part[t-1];
#pragma unroll
    for (int i = 0; i < 32; i++) g_off[base+i] = excl + loc[i];
    if (t == 1023) g_off[MTOT] = excl + s;
}

__global__ void fill_k(const int* __restrict__ edges) {
    int i = blockIdx.x*blockDim.x + threadIdx.x;       // over BG*EG
    int b = i >> 16;
    int e = i & (EG-1);
    const int* eb = edges + (size_t)b*2*EG;
    int src = eb[e]      & (NN-1);
    int dst = eb[EG + e] & (NN-1);
    int n = b*NN + dst;
    int p = atomicAdd(&g_cur[n], 1);
    g_csrc[g_off[n] + p] = src;
}

// ---------------- gather aggregation: one warp per node, no atomics ----------------
template<int F>
__device__ __forceinline__ void gather_body(const float* __restrict__ X, float* __restrict__ agg) {
    int node = blockIdx.x*8 + (threadIdx.x >> 5);      // global node id [0, MTOT)
    int lane = threadIdx.x & 31;
    int bbase = node & ~(NN-1);                        // first node of this graph
    float di = g_dinv[node];
    const float* xr = X + (size_t)node*F;
    float di2 = di*di;

    float4 a0 = *(const float4*)(xr + lane*4);
    a0.x *= di2; a0.y *= di2; a0.z *= di2; a0.w *= di2;
    float4 a1;
    if (F == 256) {
        a1 = *(const float4*)(xr + 128 + lane*4);
        a1.x *= di2; a1.y *= di2; a1.z *= di2; a1.w *= di2;
    }

    int beg = g_off[node], end = g_off[node+1];
    for (int j = beg; j < end; j++) {
        int srow = bbase + g_csrc[j];
        float nrm = g_dinv[srow] * di;
        const float* sr = X + (size_t)srow*F;
        float4 v = *(const float4*)(sr + lane*4);
        a0.x += v.x*nrm; a0.y += v.y*nrm; a0.z += v.z*nrm; a0.w += v.w*nrm;
        if (F == 256) {
            float4 w = *(const float4*)(sr + 128 + lane*4);
            a1.x += w.x*nrm; a1.y += w.y*nrm; a1.z += w.z*nrm; a1.w += w.w*nrm;
        }
    }
    float* ar = agg + (size_t)node*F;
    *(float4*)(ar + lane*4) = a0;
    if (F == 256) *(float4*)(ar + 128 + lane*4) = a1;
}

__global__ void gather1_k(const float* __restrict__ nodes) { gather_body<F0>(nodes, g_agg1); }
__global__ void gather2_k()                                { gather_body<F1>(g_h1,  g_agg2); }

// ---------------- tf32 tensor-core GEMM body: C = relu(A[MxK] @ B[KxN] + bias) ----------------
// CTA tile 128x128x32, 8 warps in 2(M)x4(N), warp tile 64x32, m16n8k8 fragments.
template<int N, int K>
__device__ __forceinline__ void mma_gemm_body(const float* __restrict__ A,
                                              const float* __restrict__ Bm,
                                              const float* __restrict__ bias,
                                              float* __restrict__ C) {
    __shared__ uint32_t As[128][36];    // [row][k] tf32, pad 36 -> frag LDS conflict-free
    __shared__ uint32_t Bs[32][136];    // [k][col] tf32, pad 136 -> frag LDS conflict-free

    const int tid  = threadIdx.x;
    const int warp = tid >> 5, lane = tid & 31;
    const int wm = warp & 1, wn = warp >> 1;   // 2x4 warp grid
    const int gid = lane >> 2, tig = lane & 3;
    const int bM = blockIdx.y * 128;
    const int bN = blockIdx.x * 128;

    float acc[4][4][4];
#pragma unroll
    for (int i = 0; i < 4; i++)
#pragma unroll
        for (int j = 0; j < 4; j++)
#pragma unroll
            for (int q = 0; q < 4; q++) acc[i][j][q] = 0.f;

    for (int kb = 0; kb < K; kb += 32) {
#pragma unroll
        for (int i = tid; i < 1024; i += 256) {
            int row = i >> 3;
            int c4  = (i & 7) * 4;
            float4 v = *(const float4*)(A + (size_t)(bM+row)*K + kb + c4);
            uint4 t = { f2tf32(v.x), f2tf32(v.y), f2tf32(v.z), f2tf32(v.w) };
            *(uint4*)(&As[row][c4]) = t;
        }
#pragma unroll
        for (int i = tid; i < 1024; i += 256) {
            int kr = i >> 5;
            int c4 = (i & 31) * 4;
            float4 v = *(const float4*)(Bm + (size_t)(kb+kr)*N + bN + c4);
            uint4 t = { f2tf32(v.x), f2tf32(v.y), f2tf32(v.z), f2tf32(v.w) };
            *(uint4*)(&Bs[kr][c4]) = t;
        }
        __syncthreads();

#pragma unroll
        for (int k8 = 0; k8 < 4; k8++) {
            const int kc = k8*8 + tig;
            uint32_t a[4][4], b[4][2];
#pragma unroll
            for (int mj = 0; mj < 4; mj++) {
                int r = wm*64 + mj*16 + gid;
                a[mj][0] = As[r  ][kc];
                a[mj][1] = As[r+8][kc];
                a[mj][2] = As[r  ][kc+4];
                a[mj][3] = As[r+8][kc+4];
            }
#pragma unroll
            for (int nj = 0; nj < 4; nj++) {
                int cN = wn*32 + nj*8 + gid;
                b[nj][0] = Bs[kc  ][cN];
                b[nj][1] = Bs[kc+4][cN];
            }
#pragma unroll
            for (int mj = 0; mj < 4; mj++)
#pragma unroll
                for (int nj = 0; nj < 4; nj++)
                    mma_tf32(acc[mj][nj], a[mj], b[nj]);
        }
        __syncthreads();
    }

#pragma unroll
    for (int mj = 0; mj < 4; mj++) {
        int row0 = bM + wm*64 + mj*16 + gid;
#pragma unroll
        for (int nj = 0; nj < 4; nj++) {
            int col = bN + wn*32 + nj*8 + 2*tig;
            float bx = bias[col], by = bias[col+1];
            float2 v0 = { fmaxf(acc[mj][nj][0] + bx, 0.f), fmaxf(acc[mj][nj][1] + by, 0.f) };
            float2 v1 = { fmaxf(acc[mj][nj][2] + bx, 0.f), fmaxf(acc[mj][nj][3] + by, 0.f) };
            *(float2*)(C + (size_t)row0*N + col)     = v0;
            *(float2*)(C + (size_t)(row0+8)*N + col) = v1;
        }
    }
}

__global__ void __launch_bounds__(256) gemm1_k(const float* __restrict__ W0,
                                               const float* __restrict__ b0) {
    mma_gemm_body<F1, F0>(g_agg1, W0, b0, g_h1);
}
__global__ void __launch_bounds__(256) gemm2_k(const float* __restrict__ W1,
                                               const float* __restrict__ b1) {
    mma_gemm_body<F2, F1>(g_agg2, W1, b1, g_h2);
}

// ---------------- fp32 f32x2 SGEMM for the head (split-write epilogue) ----------------
__device__ __forceinline__ unsigned long long pack2(float lo, float hi) {
    unsigned long long r;
    asm("mov.b64 %0, {%1, %2};" : "=l"(r) : "f"(lo), "f"(hi));
    return r;
}
__device__ __forceinline__ void unpack2(unsigned long long v, float& lo, float& hi) {
    asm("mov.b64 {%0, %1}, %2;" : "=f"(lo), "=f"(hi) : "l"(v));
}
__device__ __forceinline__ void fma2(unsigned long long& d, unsigned long long a,
                                     unsigned long long b, unsigned long long c) {
    asm("fma.rn.f32x2 %0, %1, %2, %3;" : "=l"(d) : "l"(a), "l"(b), "l"(c));
}

__global__ void __launch_bounds__(256) head_k(float* __restrict__ logits,
                                              float* __restrict__ values) {
    constexpr int Nn = 32, Kk = F2, BM = 128, BN = 32, BK = 16, TM = 8, TN = 2;
    __shared__ float As[BK][BM+4];
    __shared__ __align__(8) float Bs[BK][BN+4];
    constexpr int NTX = BN/TN, T = 256;
    constexpr int TN2 = TN/2;
    const int tid = threadIdx.x;
    const int tx = tid % NTX, ty = tid / NTX;
    const int bM = blockIdx.y * BM;

    unsigned long long acc[TM][TN2];
#pragma unroll
    for (int i = 0; i < TM; i++)
#pragma unroll
        for (int j = 0; j < TN2; j++) acc[i][j] = 0ull;

    for (int kb = 0; kb < Kk; kb += BK) {
#pragma unroll
        for (int i = tid; i < BM*BK/4; i += T) {
            int m  = i / (BK/4);
            int kq = i % (BK/4);
            float4 v = *(const float4*)(g_h2 + (size_t)(bM+m)*Kk + kb + kq*4);
            As[kq*4+0][m] = v.x; As[kq*4+1][m] = v.y;
            As[kq*4+2][m] = v.z; As[kq*4+3][m] = v.w;
        }
#pragma unroll
        for (int i = tid; i < BK*BN/4; i += T) {
            int k  = i / (BN/4);
            int nq = i % (BN/4);
            *(float4*)(&Bs[k][nq*4]) = *(const float4*)(g_Wc + (size_t)(kb+k)*Nn + nq*4);
        }
        __syncthreads();
#pragma unroll
        for (int k = 0; k < BK; k++) {
            unsigned long long ra2[TM], rb2[TN2];
#pragma unroll
            for (int i = 0; i < TM; i++) {
                float a = As[k][ty*TM + i];
                ra2[i] = pack2(a, a);
            }
#pragma unroll
            for (int j = 0; j < TN2; j++) {
                float2 b2 = *(const float2*)(&Bs[k][tx*TN + j*2]);
                rb2[j] = pack2(b2.x, b2.y);
            }
#pragma unroll
            for (int i = 0; i < TM; i++)
#pragma unroll
                for (int j = 0; j < TN2; j++)
                    fma2(acc[i][j], ra2[i], rb2[j], acc[i][j]);
        }
        __syncthreads();
    }

#pragma unroll
    for (int i = 0; i < TM; i++) {
        int row = bM + ty*TM + i;
#pragma unroll
        for (int j = 0; j < TN2; j++) {
            int col = tx*TN + j*2;
            float a0, a1;
            unpack2(acc[i][j], a0, a1);
            float v0 = a0 + g_bc[col+0];
            float v1 = a1 + g_bc[col+1];
            if (col   < NOUTD)       logits[(size_t)row*NOUTD + col  ] = v0;
            else if (col   == NOUTD) values[row] = v0;
            if (col+1 < NOUTD)       logits[(size_t)row*NOUTD + col+1] = v1;
            else if (col+1 == NOUTD) values[row] = v1;
        }
    }
}

// ---------------- pack W_logit + W_val into [K,32] padded matrix ----------------
__global__ void pack_k(const float* __restrict__ Wl, const float* __restrict__ bl,
                       const float* __restrict__ Wv, const float* __restrict__ bv) {
    int t = blockIdx.x*blockDim.x + threadIdx.x;   // F2*32
    int k = t >> 5, j = t & 31;
    float v = 0.f;
    if (j < NOUTD)       v = Wl[k*NOUTD + j];
    else if (j == NOUTD) v = Wv[k];
    g_Wc[t] = v;
    if (t < 32) {
        float b = 0.f;
        if (t < NOUTD)       b = bl[t];
        else if (t == NOUTD) b = bv[0];
        g_bc[t] = b;
    }
}

// ---------------- launch ----------------
extern "C" void kernel_launch(void* const* d_in, const int* in_sizes, int n_in,
                              void* d_out, int out_size) {
    int iNodes, iEdges, iW0, ib0, iW1, ib1, iWl, ibl, iWv, ibv;
    if (n_in >= 10 && in_sizes[0] == BG*NN*F0) {          // insertion order
        iNodes=0; iEdges=1; iW0=2; ib0=3; iW1=4; ib1=5; iWl=6; ibl=7; iWv=8; ibv=9;
    } else {                                               // sorted-key order
        iW0=0; iW1=1; iWl=2; iWv=3; ib0=4; ib1=5; ibl=6; ibv=7; iEdges=8; iNodes=9;
    }
    const float* nodes = (const float*)d_in[iNodes];
    const int*   edges = (const int*)  d_in[iEdges];
    const float* W0 = (const float*)d_in[iW0];
    const float* b0 = (const float*)d_in[ib0];
    const float* W1 = (const float*)d_in[iW1];
    const float* b1 = (const float*)d_in[ib1];
    const float* Wl = (const float*)d_in[iWl];
    const float* bl = (const float*)d_in[ibl];
    const float* Wv = (const float*)d_in[iWv];
    const float* bv = (const float*)d_in[ibv];
    float* outp   = (float*)d_out;
    float* logits = outp;
    float* values = outp + (size_t)MTOT*NOUTD;

    // CSR build + normalization
    zero_k<<<MTOT/256, 256>>>();
    cnt_k <<<BG*EG/256, 256>>>(edges);
    dinv_k<<<MTOT/256, 256>>>();
    scan_k<<<1, 1024>>>();
    fill_k<<<BG*EG/256, 256>>>(edges);

    // layer 1: gather-aggregate X (128-d) then tf32 GEMM -> relu
    gather1_k<<<MTOT/8, 256>>>(nodes);
    gemm1_k  <<<dim3(F1/128, MTOT/128), 256>>>(W0, b0);

    // layer 2: gather-aggregate h1 (256-d) then tf32 GEMM -> relu
    gather2_k<<<MTOT/8, 256>>>();
    gemm2_k  <<<dim3(F2/128, MTOT/128), 256>>>(W1, b1);

    // heads: pack [1024,19]->[1024,32], fp32 skinny GEMM with split-write epilogue
    pack_k<<<F2*32/256, 256>>>(Wl, bl, Wv, bv);
    head_k<<<dim3(1, MTOT/128), 256>>>(logits, values);
}

// round 12
// speedup vs baseline: 2.3350x; 1.1363x over previous
#include <cuda_runtime.h>
#include <cstdint>

#define BG 4
#define NN 8192
#define EG 65536
#define F0 128
#define F1 256
#define F2 1024
#define NOUTD 18
#define MTOT (BG*NN)   // 32768 rows total across graphs

// ---------------- scratch (static device globals; ONLY referenced from device code) ----------------
__device__ __align__(16) float g_dinv[MTOT];
__device__ __align__(16) float g_agg1[(size_t)MTOT*F0];
__device__ __align__(16) float g_h1  [(size_t)MTOT*F1];
__device__ __align__(16) float g_agg2[(size_t)MTOT*F1];
__device__ __align__(16) float g_h2  [(size_t)MTOT*F2];
__device__ __align__(16) float g_Wc  [F2*32];
__device__ __align__(16) float g_bc  [32];
// CSR scratch
__device__ int g_cnt [MTOT];
__device__ int g_cur [MTOT];
__device__ int g_off [MTOT+1];
__device__ int g_bsum[32];
__device__ int g_csrc[BG*EG];

// ---------------- small helpers ----------------
__device__ __forceinline__ uint32_t f2tf32(float x) {
    uint32_t r;
    asm("cvt.rn.tf32.f32 %0, %1;" : "=r"(r) : "f"(x));
    return r;
}
__device__ __forceinline__ void mma_tf32(float c[4], const uint32_t a[4], const uint32_t b[2]) {
    asm("mma.sync.aligned.m16n8k8.row.col.f32.tf32.tf32.f32 "
        "{%0,%1,%2,%3}, {%4,%5,%6,%7}, {%8,%9}, {%0,%1,%2,%3};"
        : "+f"(c[0]), "+f"(c[1]), "+f"(c[2]), "+f"(c[3])
        : "r"(a[0]), "r"(a[1]), "r"(a[2]), "r"(a[3]), "r"(b[0]), "r"(b[1]));
}

// ---------------- CSR build ----------------
__global__ void zero_k() {
    int i = blockIdx.x*blockDim.x + threadIdx.x;
    g_cnt[i] = 0;
    g_cur[i] = 0;
}

__global__ void cnt_k(const int* __restrict__ edges) {
    int i = blockIdx.x*blockDim.x + threadIdx.x;       // over BG*EG
    int b = i >> 16;
    int e = i & (EG-1);
    int dst = edges[(size_t)b*2*EG + EG + e] & (NN-1);
    atomicAdd(&g_cnt[b*NN + dst], 1);
}

__global__ void dinv_k() {
    int i = blockIdx.x*blockDim.x + threadIdx.x;
    g_dinv[i] = rsqrtf(1.0f + (float)g_cnt[i]);        // +1 self-loop
}

// parallel exclusive scan of g_cnt into g_off: 32 blocks x 1024 + tiny fixups
__global__ void __launch_bounds__(1024) scan1_k() {
    __shared__ int warp_s[32];
    int t = threadIdx.x;
    int i = blockIdx.x*1024 + t;
    int v = g_cnt[i];
    int x = v;
#pragma unroll
    for (int d = 1; d < 32; d <<= 1) {
        int y = __shfl_up_sync(~0u, x, d);
        if ((t & 31) >= d) x += y;
    }
    if ((t & 31) == 31) warp_s[t >> 5] = x;
    __syncthreads();
    if (t < 32) {
        int y = warp_s[t];
#pragma unroll
        for (int d = 1; d < 32; d <<= 1) {
            int z = __shfl_up_sync(~0u, y, d);
            if (t >= d) y += z;
        }
        warp_s[t] = y;
    }
    __syncthreads();
    int wpre = (t >> 5) ? warp_s[(t >> 5) - 1] : 0;
    int incl = x + wpre;
    g_off[i] = incl - v;                                // block-local exclusive
    if (t == 1023) g_bsum[blockIdx.x] = incl;           // block total
}

__global__ void scan2_k() {                              // 1 block, 32 threads
    int t = threadIdx.x;
    int y = g_bsum[t];
#pragma unroll
    for (int d = 1; d < 32; d <<= 1) {
        int z = __shfl_up_sync(~0u, y, d);
        if (t >= d) y += z;
    }
    g_bsum[t] = y;                                       // inclusive block sums
    if (t == 31) g_off[MTOT] = y;
}

__global__ void __launch_bounds__(1024) scan3_k() {      // add block prefixes
    int i = blockIdx.x*1024 + threadIdx.x;
    if (blockIdx.x > 0) g_off[i] += g_bsum[blockIdx.x - 1];
}

__global__ void fill_k(const int* __restrict__ edges) {
    int i = blockIdx.x*blockDim.x + threadIdx.x;       // over BG*EG
    int b = i >> 16;
    int e = i & (EG-1);
    const int* eb = edges + (size_t)b*2*EG;
    int src = eb[e]      & (NN-1);
    int dst = eb[EG + e] & (NN-1);
    int n = b*NN + dst;
    int p = atomicAdd(&g_cur[n], 1);
    g_csrc[g_off[n] + p] = src;
}

// ---------------- gather aggregation: one warp per node, no atomics ----------------
template<int F>
__device__ __forceinline__ void gather_body(const float* __restrict__ X, float* __restrict__ agg) {
    int node = blockIdx.x*8 + (threadIdx.x >> 5);      // global node id [0, MTOT)
    int lane = threadIdx.x & 31;
    int bbase = node & ~(NN-1);                        // first node of this graph
    float di = g_dinv[node];
    const float* xr = X + (size_t)node*F;
    float di2 = di*di;

    float4 a0 = *(const float4*)(xr + lane*4);
    a0.x *= di2; a0.y *= di2; a0.z *= di2; a0.w *= di2;
    float4 a1;
    if (F == 256) {
        a1 = *(const float4*)(xr + 128 + lane*4);
        a1.x *= di2; a1.y *= di2; a1.z *= di2; a1.w *= di2;
    }

    int beg = g_off[node], end = g_off[node+1];
    for (int j = beg; j < end; j++) {
        int srow = bbase + g_csrc[j];
        float nrm = g_dinv[srow] * di;
        const float* sr = X + (size_t)srow*F;
        float4 v = *(const float4*)(sr + lane*4);
        a0.x += v.x*nrm; a0.y += v.y*nrm; a0.z += v.z*nrm; a0.w += v.w*nrm;
        if (F == 256) {
            float4 w = *(const float4*)(sr + 128 + lane*4);
            a1.x += w.x*nrm; a1.y += w.y*nrm; a1.z += w.z*nrm; a1.w += w.w*nrm;
        }
    }
    float* ar = agg + (size_t)node*F;
    *(float4*)(ar + lane*4) = a0;
    if (F == 256) *(float4*)(ar + 128 + lane*4) = a1;
}

__global__ void gather1_k(const float* __restrict__ nodes) { gather_body<F0>(nodes, g_agg1); }
__global__ void gather2_k()                                { gather_body<F1>(g_h1,  g_agg2); }

// ---------------- tf32 tensor-core GEMM body: C = relu(A[MxK] @ B[KxN] + bias) ----------------
// CTA tile 128x128x32, 8 warps in 2(M)x4(N), warp tile 64x32, m16n8k8 fragments.
template<int N, int K>
__device__ __forceinline__ void mma_gemm_body(const float* __restrict__ A,
                                              const float* __restrict__ Bm,
                                              const float* __restrict__ bias,
                                              float* __restrict__ C) {
    __shared__ uint32_t As[128][36];    // [row][k] tf32, pad 36 -> frag LDS conflict-free
    __shared__ uint32_t Bs[32][136];    // [k][col] tf32, pad 136 -> frag LDS conflict-free

    const int tid  = threadIdx.x;
    const int warp = tid >> 5, lane = tid & 31;
    const int wm = warp & 1, wn = warp >> 1;   // 2x4 warp grid
    const int gid = lane >> 2, tig = lane & 3;
    const int bM = blockIdx.y * 128;
    const int bN = blockIdx.x * 128;

    float acc[4][4][4];
#pragma unroll
    for (int i = 0; i < 4; i++)
#pragma unroll
        for (int j = 0; j < 4; j++)
#pragma unroll
            for (int q = 0; q < 4; q++) acc[i][j][q] = 0.f;

    for (int kb = 0; kb < K; kb += 32) {
#pragma unroll
        for (int i = tid; i < 1024; i += 256) {
            int row = i >> 3;
            int c4  = (i & 7) * 4;
            float4 v = *(const float4*)(A + (size_t)(bM+row)*K + kb + c4);
            uint4 t = { f2tf32(v.x), f2tf32(v.y), f2tf32(v.z), f2tf32(v.w) };
            *(uint4*)(&As[row][c4]) = t;
        }
#pragma unroll
        for (int i = tid; i < 1024; i += 256) {
            int kr = i >> 5;
            int c4 = (i & 31) * 4;
            float4 v = *(const float4*)(Bm + (size_t)(kb+kr)*N + bN + c4);
            uint4 t = { f2tf32(v.x), f2tf32(v.y), f2tf32(v.z), f2tf32(v.w) };
            *(uint4*)(&Bs[kr][c4]) = t;
        }
        __syncthreads();

#pragma unroll
        for (int k8 = 0; k8 < 4; k8++) {
            const int kc = k8*8 + tig;
            uint32_t a[4][4], b[4][2];
#pragma unroll
            for (int mj = 0; mj < 4; mj++) {
                int r = wm*64 + mj*16 + gid;
                a[mj][0] = As[r  ][kc];
                a[mj][1] = As[r+8][kc];
                a[mj][2] = As[r  ][kc+4];
                a[mj][3] = As[r+8][kc+4];
            }
#pragma unroll
            for (int nj = 0; nj < 4; nj++) {
                int cN = wn*32 + nj*8 + gid;
                b[nj][0] = Bs[kc  ][cN];
                b[nj][1] = Bs[kc+4][cN];
            }
#pragma unroll
            for (int mj = 0; mj < 4; mj++)
#pragma unroll
                for (int nj = 0; nj < 4; nj++)
                    mma_tf32(acc[mj][nj], a[mj], b[nj]);
        }
        __syncthreads();
    }

#pragma unroll
    for (int mj = 0; mj < 4; mj++) {
        int row0 = bM + wm*64 + mj*16 + gid;
#pragma unroll
        for (int nj = 0; nj < 4; nj++) {
            int col = bN + wn*32 + nj*8 + 2*tig;
            float bx = bias[col], by = bias[col+1];
            float2 v0 = { fmaxf(acc[mj][nj][0] + bx, 0.f), fmaxf(acc[mj][nj][1] + by, 0.f) };
            float2 v1 = { fmaxf(acc[mj][nj][2] + bx, 0.f), fmaxf(acc[mj][nj][3] + by, 0.f) };
            *(float2*)(C + (size_t)row0*N + col)     = v0;
            *(float2*)(C + (size_t)(row0+8)*N + col) = v1;
        }
    }
}

__global__ void __launch_bounds__(256) gemm1_k(const float* __restrict__ W0,
                                               const float* __restrict__ b0) {
    mma_gemm_body<F1, F0>(g_agg1, W0, b0, g_h1);
}
__global__ void __launch_bounds__(256) gemm2_k(const float* __restrict__ W1,
                                               const float* __restrict__ b1) {
    mma_gemm_body<F2, F1>(g_agg2, W1, b1, g_h2);
}

// ---------------- head: split-tf32 (3xTF32) tensor GEMM, near-fp32 accuracy ----------------
// C[32768,32] = g_h2[32768,1024] @ g_Wc[1024,32] + g_bc, split-write epilogue.
// 8 warps x 16-row slices; each warp covers all N=32 (4 x m16n8 tiles).
__global__ void __launch_bounds__(256) head_k(float* __restrict__ logits,
                                              float* __restrict__ values) {
    __shared__ uint32_t Ah[128][36], Al[128][36];   // hi/lo tf32 of A tile
    __shared__ uint32_t Bh[32][36],  Bl[32][36];    // hi/lo tf32 of B tile [k][n]

    const int tid  = threadIdx.x;
    const int warp = tid >> 5, lane = tid & 31;
    const int gid = lane >> 2, tig = lane & 3;
    const int bM = blockIdx.x * 128;

    float acc[4][4];
#pragma unroll
    for (int j = 0; j < 4; j++)
#pragma unroll
        for (int q = 0; q < 4; q++) acc[j][q] = 0.f;

    for (int kb = 0; kb < F2; kb += 32) {
        // A tile 128x32: 1024 float4 / 256 threads = 4 each
#pragma unroll
        for (int i = tid; i < 1024; i += 256) {
            int row = i >> 3;
            int c4  = (i & 7) * 4;
            float4 v = *(const float4*)(g_h2 + (size_t)(bM+row)*F2 + kb + c4);
            uint32_t hx = f2tf32(v.x), hy = f2tf32(v.y), hz = f2tf32(v.z), hw = f2tf32(v.w);
            uint4 th = { hx, hy, hz, hw };
            uint4 tl = { f2tf32(v.x - __uint_as_float(hx)),
                         f2tf32(v.y - __uint_as_float(hy)),
                         f2tf32(v.z - __uint_as_float(hz)),
                         f2tf32(v.w - __uint_as_float(hw)) };
            *(uint4*)(&Ah[row][c4]) = th;
            *(uint4*)(&Al[row][c4]) = tl;
        }
        // B tile 32x32: 256 float4, 1 per thread
        {
            int kr = tid >> 3;
            int c4 = (tid & 7) * 4;
            float4 v = *(const float4*)(g_Wc + (size_t)(kb+kr)*32 + c4);
            uint32_t hx = f2tf32(v.x), hy = f2tf32(v.y), hz = f2tf32(v.z), hw = f2tf32(v.w);
            uint4 th = { hx, hy, hz, hw };
            uint4 tl = { f2tf32(v.x - __uint_as_float(hx)),
                         f2tf32(v.y - __uint_as_float(hy)),
                         f2tf32(v.z - __uint_as_float(hz)),
                         f2tf32(v.w - __uint_as_float(hw)) };
            *(uint4*)(&Bh[kr][c4]) = th;
            *(uint4*)(&Bl[kr][c4]) = tl;
        }
        __syncthreads();

#pragma unroll
        for (int k8 = 0; k8 < 4; k8++) {
            const int kc = k8*8 + tig;
            int r = warp*16 + gid;
            uint32_t ah[4], al[4];
            ah[0] = Ah[r  ][kc]; ah[1] = Ah[r+8][kc]; ah[2] = Ah[r  ][kc+4]; ah[3] = Ah[r+8][kc+4];
            al[0] = Al[r  ][kc]; al[1] = Al[r+8][kc]; al[2] = Al[r  ][kc+4]; al[3] = Al[r+8][kc+4];
#pragma unroll
            for (int nj = 0; nj < 4; nj++) {
                int cN = nj*8 + gid;
                uint32_t bh[2] = { Bh[kc][cN], Bh[kc+4][cN] };
                uint32_t bl[2] = { Bl[kc][cN], Bl[kc+4][cN] };
                mma_tf32(acc[nj], ah, bh);
                mma_tf32(acc[nj], ah, bl);
                mma_tf32(acc[nj], al, bh);
            }
        }
        __syncthreads();
    }

    // epilogue: split-write (cols 0..17 -> logits, col 18 -> values, 19..31 dropped)
    int row0 = bM + warp*16 + gid;
#pragma unroll
    for (int nj = 0; nj < 4; nj++) {
        int col = nj*8 + 2*tig;
        float b0v = g_bc[col], b1v = g_bc[col+1];
        float c00 = acc[nj][0] + b0v, c01 = acc[nj][1] + b1v;   // row0
        float c10 = acc[nj][2] + b0v, c11 = acc[nj][3] + b1v;   // row0+8
        if (col < NOUTD) {
            logits[(size_t)row0*NOUTD + col]     = c00;
            logits[(size_t)(row0+8)*NOUTD + col] = c10;
        } else if (col == NOUTD) {
            values[row0]   = c00;
            values[row0+8] = c10;
        }
        if (col+1 < NOUTD) {
            logits[(size_t)row0*NOUTD + col+1]     = c01;
            logits[(size_t)(row0+8)*NOUTD + col+1] = c11;
        }
    }
}

// ---------------- pack W_logit + W_val into [K,32] padded matrix ----------------
__global__ void pack_k(const float* __restrict__ Wl, const float* __restrict__ bl,
                       const float* __restrict__ Wv, const float* __restrict__ bv) {
    int t = blockIdx.x*blockDim.x + threadIdx.x;   // F2*32
    int k = t >> 5, j = t & 31;
    float v = 0.f;
    if (j < NOUTD)       v = Wl[k*NOUTD + j];
    else if (j == NOUTD) v = Wv[k];
    g_Wc[t] = v;
    if (t < 32) {
        float b = 0.f;
        if (t < NOUTD)       b = bl[t];
        else if (t == NOUTD) b = bv[0];
        g_bc[t] = b;
    }
}

// ---------------- launch ----------------
extern "C" void kernel_launch(void* const* d_in, const int* in_sizes, int n_in,
                              void* d_out, int out_size) {
    int iNodes, iEdges, iW0, ib0, iW1, ib1, iWl, ibl, iWv, ibv;
    if (n_in >= 10 && in_sizes[0] == BG*NN*F0) {          // insertion order
        iNodes=0; iEdges=1; iW0=2; ib0=3; iW1=4; ib1=5; iWl=6; ibl=7; iWv=8; ibv=9;
    } else {                                               // sorted-key order
        iW0=0; iW1=1; iWl=2; iWv=3; ib0=4; ib1=5; ibl=6; ibv=7; iEdges=8; iNodes=9;
    }
    const float* nodes = (const float*)d_in[iNodes];
    const int*   edges = (const int*)  d_in[iEdges];
    const float* W0 = (const float*)d_in[iW0];
    const float* b0 = (const float*)d_in[ib0];
    const float* W1 = (const float*)d_in[iW1];
    const float* b1 = (const float*)d_in[ib1];
    const float* Wl = (const float*)d_in[iWl];
    const float* bl = (const float*)d_in[ibl];
    const float* Wv = (const float*)d_in[iWv];
    const float* bv = (const float*)d_in[ibv];
    float* outp   = (float*)d_out;
    float* logits = outp;
    float* values = outp + (size_t)MTOT*NOUTD;

    // CSR build + normalization
    zero_k <<<MTOT/256, 256>>>();
    cnt_k  <<<BG*EG/256, 256>>>(edges);
    dinv_k <<<MTOT/256, 256>>>();
    scan1_k<<<32, 1024>>>();
    scan2_k<<<1, 32>>>();
    scan3_k<<<32, 1024>>>();
    fill_k <<<BG*EG/256, 256>>>(edges);

    // layer 1: gather-aggregate X (128-d) then tf32 GEMM -> relu
    gather1_k<<<MTOT/8, 256>>>(nodes);
    gemm1_k  <<<dim3(F1/128, MTOT/128), 256>>>(W0, b0);

    // layer 2: gather-aggregate h1 (256-d) then tf32 GEMM -> relu
    gather2_k<<<MTOT/8, 256>>>();
    gemm2_k  <<<dim3(F2/128, MTOT/128), 256>>>(W1, b1);

    // heads: pack [1024,19]->[1024,32], split-tf32 head GEMM
    pack_k<<<F2*32/256, 256>>>(Wl, bl, Wv, bv);
    head_k<<<MTOT/128, 256>>>(logits, values);
}

// round 13
// speedup vs baseline: 2.8823x; 1.2344x over previous
#include <cuda_runtime.h>
#include <cstdint>

#define BG 4
#define NN 8192
#define EG 65536
#define F0 128
#define F1 256
#define F2 1024
#define NOUTD 18
#define NHEAD 24
#define MTOT (BG*NN)   // 32768 rows total across graphs

// ---------------- scratch (static device globals; ONLY referenced from device code) ----------------
__device__ __align__(16) float g_dinv[MTOT];
__device__ __align__(16) float g_agg1[(size_t)MTOT*F0];
__device__ __align__(16) float g_h1  [(size_t)MTOT*F1];
__device__ __align__(16) float g_agg2[(size_t)MTOT*F1];
__device__ __align__(16) float g_h2  [(size_t)MTOT*F2];
__device__ __align__(16) float g_Wc  [F2*NHEAD];
__device__ __align__(16) float g_bc  [NHEAD];
// CSR scratch
__device__ int g_cnt [MTOT];
__device__ int g_cur [MTOT];
__device__ int g_off [MTOT+1];
__device__ int g_bsum[32];
__device__ int g_csrc[BG*EG];

// ---------------- small helpers ----------------
__device__ __forceinline__ uint32_t f2tf32(float x) {
    uint32_t r;
    asm("cvt.rn.tf32.f32 %0, %1;" : "=r"(r) : "f"(x));
    return r;
}
__device__ __forceinline__ void mma_tf32(float c[4], const uint32_t a[4], const uint32_t b[2]) {
    asm("mma.sync.aligned.m16n8k8.row.col.f32.tf32.tf32.f32 "
        "{%0,%1,%2,%3}, {%4,%5,%6,%7}, {%8,%9}, {%0,%1,%2,%3};"
        : "+f"(c[0]), "+f"(c[1]), "+f"(c[2]), "+f"(c[3])
        : "r"(a[0]), "r"(a[1]), "r"(a[2]), "r"(a[3]), "r"(b[0]), "r"(b[1]));
}

// ---------------- CSR build ----------------
__global__ void zero_k() {
    int i = blockIdx.x*blockDim.x + threadIdx.x;
    g_cnt[i] = 0;
}

__global__ void cnt_k(const int* __restrict__ edges) {
    int i = blockIdx.x*blockDim.x + threadIdx.x;       // over BG*EG
    int b = i >> 16;
    int e = i & (EG-1);
    int dst = edges[(size_t)b*2*EG + EG + e] & (NN-1);
    atomicAdd(&g_cnt[b*NN + dst], 1);
}

// scan + dinv + cur-zero fused: 32 blocks x 1024
__global__ void __launch_bounds__(1024) scan1_k() {
    __shared__ int warp_s[32];
    int t = threadIdx.x;
    int i = blockIdx.x*1024 + t;
    int v = g_cnt[i];
    g_dinv[i] = rsqrtf(1.0f + (float)v);               // +1 self-loop
    g_cur[i] = 0;
    int x = v;
#pragma unroll
    for (int d = 1; d < 32; d <<= 1) {
        int y = __shfl_up_sync(~0u, x, d);
        if ((t & 31) >= d) x += y;
    }
    if ((t & 31) == 31) warp_s[t >> 5] = x;
    __syncthreads();
    if (t < 32) {
        int y = warp_s[t];
#pragma unroll
        for (int d = 1; d < 32; d <<= 1) {
            int z = __shfl_up_sync(~0u, y, d);
            if (t >= d) y += z;
        }
        warp_s[t] = y;
    }
    __syncthreads();
    int wpre = (t >> 5) ? warp_s[(t >> 5) - 1] : 0;
    int incl = x + wpre;
    g_off[i] = incl - v;                                // block-local exclusive
    if (t == 1023) g_bsum[blockIdx.x] = incl;           // block total
}

__global__ void scan2_k() {                              // 1 block, 32 threads
    int t = threadIdx.x;
    int y = g_bsum[t];
#pragma unroll
    for (int d = 1; d < 32; d <<= 1) {
        int z = __shfl_up_sync(~0u, y, d);
        if (t >= d) y += z;
    }
    g_bsum[t] = y;                                       // inclusive block sums
    if (t == 31) g_off[MTOT] = y;
}

__global__ void __launch_bounds__(1024) scan3_k() {      // add block prefixes
    int i = blockIdx.x*1024 + threadIdx.x;
    if (blockIdx.x > 0) g_off[i] += g_bsum[blockIdx.x - 1];
}

__global__ void fill_k(const int* __restrict__ edges) {
    int i = blockIdx.x*blockDim.x + threadIdx.x;       // over BG*EG
    int b = i >> 16;
    int e = i & (EG-1);
    const int* eb = edges + (size_t)b*2*EG;
    int src = eb[e]      & (NN-1);
    int dst = eb[EG + e] & (NN-1);
    int n = b*NN + dst;
    int p = atomicAdd(&g_cur[n], 1);
    g_csrc[g_off[n] + p] = src;
}

// ---------------- gather aggregation: one warp per node, no atomics ----------------
template<int F>
__device__ __forceinline__ void gather_body(const float* __restrict__ X, float* __restrict__ agg) {
    int node = blockIdx.x*8 + (threadIdx.x >> 5);      // global node id [0, MTOT)
    int lane = threadIdx.x & 31;
    int bbase = node & ~(NN-1);                        // first node of this graph
    float di = g_dinv[node];
    const float* xr = X + (size_t)node*F;
    float di2 = di*di;

    float4 a0 = *(const float4*)(xr + lane*4);
    a0.x *= di2; a0.y *= di2; a0.z *= di2; a0.w *= di2;
    float4 a1;
    if (F == 256) {
        a1 = *(const float4*)(xr + 128 + lane*4);
        a1.x *= di2; a1.y *= di2; a1.z *= di2; a1.w *= di2;
    }

    int beg = g_off[node], end = g_off[node+1];
    for (int j = beg; j < end; j++) {
        int srow = bbase + g_csrc[j];
        float nrm = g_dinv[srow] * di;
        const float* sr = X + (size_t)srow*F;
        float4 v = *(const float4*)(sr + lane*4);
        a0.x += v.x*nrm; a0.y += v.y*nrm; a0.z += v.z*nrm; a0.w += v.w*nrm;
        if (F == 256) {
            float4 w = *(const float4*)(sr + 128 + lane*4);
            a1.x += w.x*nrm; a1.y += w.y*nrm; a1.z += w.z*nrm; a1.w += w.w*nrm;
        }
    }
    float* ar = agg + (size_t)node*F;
    *(float4*)(ar + lane*4) = a0;
    if (F == 256) *(float4*)(ar + 128 + lane*4) = a1;
}

__global__ void gather1_k(const float* __restrict__ nodes) { gather_body<F0>(nodes, g_agg1); }
__global__ void gather2_k()                                { gather_body<F1>(g_h1,  g_agg2); }

// ---------------- tf32 tensor GEMM, 2-stage pipelined: C = relu(A @ B + bias) ----------------
// CTA tile 128x128x16, 8 warps 2(M)x4(N), one __syncthreads per k-iter, LDG overlapped with MMA.
template<int N, int K>
__device__ __forceinline__ void mma_gemm_body(const float* __restrict__ A,
                                              const float* __restrict__ Bm,
                                              const float* __restrict__ bias,
                                              float* __restrict__ C) {
    __shared__ uint32_t As[2][128][20];   // [stage][row][k]; stride 20 -> 20g+t mod32 distinct
    __shared__ uint32_t Bs[2][16][136];   // [stage][k][col]; stride 136 -> 8t+g mod32 distinct

    const int tid  = threadIdx.x;
    const int warp = tid >> 5, lane = tid & 31;
    const int wm = warp & 1, wn = warp >> 1;
    const int gid = lane >> 2, tig = lane & 3;
    const int bM = blockIdx.y * 128;
    const int bN = blockIdx.x * 128;

    // per-thread load slots: A: idx=tid+j*256 -> row=idx>>2, c4=(idx&3)*4
    //                        B: kr=idx>>5, c4=(idx&31)*4
    float acc[4][4][4];
#pragma unroll
    for (int i = 0; i < 4; i++)
#pragma unroll
        for (int j = 0; j < 4; j++)
#pragma unroll
            for (int q = 0; q < 4; q++) acc[i][j][q] = 0.f;

    // preload k-block 0 into stage 0
#pragma unroll
    for (int j = 0; j < 2; j++) {
        int idx = tid + j*256;
        int row = idx >> 2, c4 = (idx & 3)*4;
        float4 v = *(const float4*)(A + (size_t)(bM+row)*K + c4);
        uint4 t = { f2tf32(v.x), f2tf32(v.y), f2tf32(v.z), f2tf32(v.w) };
        *(uint4*)(&As[0][row][c4]) = t;
        int kr = idx >> 5, c42 = (idx & 31)*4;
        float4 w = *(const float4*)(Bm + (size_t)kr*N + bN + c42);
        uint4 t2 = { f2tf32(w.x), f2tf32(w.y), f2tf32(w.z), f2tf32(w.w) };
        *(uint4*)(&Bs[0][kr][c42]) = t2;
    }
    __syncthreads();

    constexpr int NIT = K/16;
    float4 va[2], vb[2];
    for (int it = 0; it < NIT; it++) {
        const int cur = it & 1, nxt = cur ^ 1;
        if (it + 1 < NIT) {
            const int kb = (it+1)*16;
#pragma unroll
            for (int j = 0; j < 2; j++) {
                int idx = tid + j*256;
                int row = idx >> 2, c4 = (idx & 3)*4;
                va[j] = *(const float4*)(A + (size_t)(bM+row)*K + kb + c4);
                int kr = idx >> 5, c42 = (idx & 31)*4;
                vb[j] = *(const float4*)(Bm + (size_t)(kb+kr)*N + bN + c42);
            }
        }
        // MMA on current stage
#pragma unroll
        for (int k8 = 0; k8 < 2; k8++) {
            const int kc = k8*8 + tig;
            uint32_t a[4][4], b[4][2];
#pragma unroll
            for (int mj = 0; mj < 4; mj++) {
                int r = wm*64 + mj*16 + gid;
                a[mj][0] = As[cur][r  ][kc];
                a[mj][1] = As[cur][r+8][kc];
                a[mj][2] = As[cur][r  ][kc+4];
                a[mj][3] = As[cur][r+8][kc+4];
            }
#pragma unroll
            for (int nj = 0; nj < 4; nj++) {
                int cN = wn*32 + nj*8 + gid;
                b[nj][0] = Bs[cur][kc  ][cN];
                b[nj][1] = Bs[cur][kc+4][cN];
            }
#pragma unroll
            for (int mj = 0; mj < 4; mj++)
#pragma unroll
                for (int nj = 0; nj < 4; nj++)
                    mma_tf32(acc[mj][nj], a[mj], b[nj]);
        }
        if (it + 1 < NIT) {
#pragma unroll
            for (int j = 0; j < 2; j++) {
                int idx = tid + j*256;
                int row = idx >> 2, c4 = (idx & 3)*4;
                uint4 t = { f2tf32(va[j].x), f2tf32(va[j].y), f2tf32(va[j].z), f2tf32(va[j].w) };
                *(uint4*)(&As[nxt][row][c4]) = t;
                int kr = idx >> 5, c42 = (idx & 31)*4;
                uint4 t2 = { f2tf32(vb[j].x), f2tf32(vb[j].y), f2tf32(vb[j].z), f2tf32(vb[j].w) };
                *(uint4*)(&Bs[nxt][kr][c42]) = t2;
            }
        }
        __syncthreads();
    }

#pragma unroll
    for (int mj = 0; mj < 4; mj++) {
        int row0 = bM + wm*64 + mj*16 + gid;
#pragma unroll
        for (int nj = 0; nj < 4; nj++) {
            int col = bN + wn*32 + nj*8 + 2*tig;
            float bx = bias[col], by = bias[col+1];
            float2 v0 = { fmaxf(acc[mj][nj][0] + bx, 0.f), fmaxf(acc[mj][nj][1] + by, 0.f) };
            float2 v1 = { fmaxf(acc[mj][nj][2] + bx, 0.f), fmaxf(acc[mj][nj][3] + by, 0.f) };
            *(float2*)(C + (size_t)row0*N + col)     = v0;
            *(float2*)(C + (size_t)(row0+8)*N + col) = v1;
        }
    }
}

__global__ void __launch_bounds__(256) gemm1_k(const float* __restrict__ W0,
                                               const float* __restrict__ b0) {
    mma_gemm_body<F1, F0>(g_agg1, W0, b0, g_h1);
}
__global__ void __launch_bounds__(256) gemm2_k(const float* __restrict__ W1,
                                               const float* __restrict__ b1) {
    mma_gemm_body<F2, F1>(g_agg2, W1, b1, g_h2);
}

// ---------------- head: split-tf32 (3xTF32), N=24 packed ----------------
// C[32768,24] = g_h2 @ g_Wc + g_bc; cols 0..17 -> logits, 18 -> values.
__global__ void __launch_bounds__(256) head_k(float* __restrict__ logits,
                                              float* __restrict__ values) {
    __shared__ uint32_t Ah[128][36], Al[128][36];   // hi/lo tf32 of A tile
    __shared__ uint32_t Bh[32][36],  Bl[32][36];    // hi/lo tf32 of B tile [k][n<24]

    const int tid  = threadIdx.x;
    const int warp = tid >> 5, lane = tid & 31;
    const int gid = lane >> 2, tig = lane & 3;
    const int bM = blockIdx.x * 128;

    float acc[3][4];
#pragma unroll
    for (int j = 0; j < 3; j++)
#pragma unroll
        for (int q = 0; q < 4; q++) acc[j][q] = 0.f;

    for (int kb = 0; kb < F2; kb += 32) {
#pragma unroll
        for (int i = tid; i < 1024; i += 256) {
            int row = i >> 3;
            int c4  = (i & 7) * 4;
            float4 v = *(const float4*)(g_h2 + (size_t)(bM+row)*F2 + kb + c4);
            uint32_t hx = f2tf32(v.x), hy = f2tf32(v.y), hz = f2tf32(v.z), hw = f2tf32(v.w);
            uint4 th = { hx, hy, hz, hw };
            uint4 tl = { f2tf32(v.x - __uint_as_float(hx)),
                         f2tf32(v.y - __uint_as_float(hy)),
                         f2tf32(v.z - __uint_as_float(hz)),
                         f2tf32(v.w - __uint_as_float(hw)) };
            *(uint4*)(&Ah[row][c4]) = th;
            *(uint4*)(&Al[row][c4]) = tl;
        }
        // B tile 32x24: 192 float4
        if (tid < 192) {
            int kr = tid / 6;
            int c4 = (tid % 6) * 4;
            float4 v = *(const float4*)(g_Wc + (size_t)(kb+kr)*NHEAD + c4);
            uint32_t hx = f2tf32(v.x), hy = f2tf32(v.y), hz = f2tf32(v.z), hw = f2tf32(v.w);
            uint4 th = { hx, hy, hz, hw };
            uint4 tl = { f2tf32(v.x - __uint_as_float(hx)),
                         f2tf32(v.y - __uint_as_float(hy)),
                         f2tf32(v.z - __uint_as_float(hz)),
                         f2tf32(v.w - __uint_as_float(hw)) };
            *(uint4*)(&Bh[kr][c4]) = th;
            *(uint4*)(&Bl[kr][c4]) = tl;
        }
        __syncthreads();

#pragma unroll
        for (int k8 = 0; k8 < 4; k8++) {
            const int kc = k8*8 + tig;
            int r = warp*16 + gid;
            uint32_t ah[4], al[4];
            ah[0] = Ah[r  ][kc]; ah[1] = Ah[r+8][kc]; ah[2] = Ah[r  ][kc+4]; ah[3] = Ah[r+8][kc+4];
            al[0] = Al[r  ][kc]; al[1] = Al[r+8][kc]; al[2] = Al[r  ][kc+4]; al[3] = Al[r+8][kc+4];
#pragma unroll
            for (int nj = 0; nj < 3; nj++) {
                int cN = nj*8 + gid;
                uint32_t bh[2] = { Bh[kc][cN], Bh[kc+4][cN] };
                uint32_t bl[2] = { Bl[kc][cN], Bl[kc+4][cN] };
                mma_tf32(acc[nj], ah, bh);
                mma_tf32(acc[nj], ah, bl);
                mma_tf32(acc[nj], al, bh);
            }
        }
        __syncthreads();
    }

    int row0 = bM + warp*16 + gid;
#pragma unroll
    for (int nj = 0; nj < 3; nj++) {
        int col = nj*8 + 2*tig;
        float b0v = g_bc[col], b1v = g_bc[col+1];
        float c00 = acc[nj][0] + b0v, c01 = acc[nj][1] + b1v;   // row0
        float c10 = acc[nj][2] + b0v, c11 = acc[nj][3] + b1v;   // row0+8
        if (col < NOUTD) {
            logits[(size_t)row0*NOUTD + col]     = c00;
            logits[(size_t)(row0+8)*NOUTD + col] = c10;
        } else if (col == NOUTD) {
            values[row0]   = c00;
            values[row0+8] = c10;
        }
        if (col+1 < NOUTD) {
            logits[(size_t)row0*NOUTD + col+1]     = c01;
            logits[(size_t)(row0+8)*NOUTD + col+1] = c11;
        }
    }
}

// ---------------- pack W_logit + W_val into [K,24] padded matrix ----------------
__global__ void pack_k(const float* __restrict__ Wl, const float* __restrict__ bl,
                       const float* __restrict__ Wv, const float* __restrict__ bv) {
    int t = blockIdx.x*blockDim.x + threadIdx.x;   // F2*NHEAD
    int k = t / NHEAD, j = t % NHEAD;
    float v = 0.f;
    if (j < NOUTD)       v = Wl[k*NOUTD + j];
    else if (j == NOUTD) v = Wv[k];
    g_Wc[t] = v;
    if (t < NHEAD) {
        float b = 0.f;
        if (t < NOUTD)       b = bl[t];
        else if (t == NOUTD) b = bv[0];
        g_bc[t] = b;
    }
}

// ---------------- launch ----------------
extern "C" void kernel_launch(void* const* d_in, const int* in_sizes, int n_in,
                              void* d_out, int out_size) {
    int iNodes, iEdges, iW0, ib0, iW1, ib1, iWl, ibl, iWv, ibv;
    if (n_in >= 10 && in_sizes[0] == BG*NN*F0) {          // insertion order
        iNodes=0; iEdges=1; iW0=2; ib0=3; iW1=4; ib1=5; iWl=6; ibl=7; iWv=8; ibv=9;
    } else {                                               // sorted-key order
        iW0=0; iW1=1; iWl=2; iWv=3; ib0=4; ib1=5; ibl=6; ibv=7; iEdges=8; iNodes=9;
    }
    const float* nodes = (const float*)d_in[iNodes];
    const int*   edges = (const int*)  d_in[iEdges];
    const float* W0 = (const float*)d_in[iW0];
    const float* b0 = (const float*)d_in[ib0];
    const float* W1 = (const float*)d_in[iW1];
    const float* b1 = (const float*)d_in[ib1];
    const float* Wl = (const float*)d_in[iWl];
    const float* bl = (const float*)d_in[ibl];
    const float* Wv = (const float*)d_in[iWv];
    const float* bv = (const float*)d_in[ibv];
    float* outp   = (float*)d_out;
    float* logits = outp;
    float* values = outp + (size_t)MTOT*NOUTD;

    // CSR build + normalization
    zero_k <<<MTOT/256, 256>>>();
    cnt_k  <<<BG*EG/256, 256>>>(edges);
    scan1_k<<<32, 1024>>>();
    scan2_k<<<1, 32>>>();
    scan3_k<<<32, 1024>>>();
    fill_k <<<BG*EG/256, 256>>>(edges);

    // layer 1: gather-aggregate X (128-d) then tf32 GEMM -> relu
    gather1_k<<<MTOT/8, 256>>>(nodes);
    gemm1_k  <<<dim3(F1/128, MTOT/128), 256>>>(W0, b0);

    // layer 2: gather-aggregate h1 (256-d) then tf32 GEMM -> relu
    gather2_k<<<MTOT/8, 256>>>();
    gemm2_k  <<<dim3(F2/128, MTOT/128), 256>>>(W1, b1);

    // heads: pack [1024,19]->[1024,24], split-tf32 head GEMM
    pack_k<<<F2*NHEAD/256, 256>>>(Wl, bl, Wv, bv);
    head_k<<<MTOT/128, 256>>>(logits, values);
}

// round 14
// speedup vs baseline: 3.4340x; 1.1914x over previous
#include <cuda_runtime.h>
#include <cstdint>

#define BG 4
#define NN 8192
#define EG 65536
#define F0 128
#define F1 256
#define F2 1024
#define NOUTD 18
#define NHEAD 24
#define MTOT (BG*NN)   // 32768 rows total across graphs

// ---------------- scratch (static device globals; ONLY referenced from device code) ----------------
__device__ __align__(16) float g_dinv[MTOT];
__device__ __align__(16) float g_agg1[(size_t)MTOT*F0];
__device__ __align__(16) float g_h1  [(size_t)MTOT*F1];
__device__ __align__(16) float g_agg2[(size_t)MTOT*F1];
__device__ __align__(16) float g_Wc  [F2*NHEAD];
__device__ __align__(16) float g_bc  [NHEAD];
__device__ __align__(16) float g_hp  [8*(size_t)MTOT*NHEAD];   // head k-partials
// CSR scratch
__device__ int g_cnt [MTOT];
__device__ int g_cur [MTOT];
__device__ int g_off [MTOT+1];
__device__ int g_bsum[32];
__device__ int g_csrc[BG*EG];

// ---------------- small helpers ----------------
__device__ __forceinline__ uint32_t f2tf32(float x) {
    uint32_t r;
    asm("cvt.rn.tf32.f32 %0, %1;" : "=r"(r) : "f"(x));
    return r;
}
__device__ __forceinline__ void mma_tf32(float c[4], const uint32_t a[4], const uint32_t b[2]) {
    asm("mma.sync.aligned.m16n8k8.row.col.f32.tf32.tf32.f32 "
        "{%0,%1,%2,%3}, {%4,%5,%6,%7}, {%8,%9}, {%0,%1,%2,%3};"
        : "+f"(c[0]), "+f"(c[1]), "+f"(c[2]), "+f"(c[3])
        : "r"(a[0]), "r"(a[1]), "r"(a[2]), "r"(a[3]), "r"(b[0]), "r"(b[1]));
}

// ---------------- CSR build ----------------
__global__ void zero_k() {
    int i = blockIdx.x*blockDim.x + threadIdx.x;
    g_cnt[i] = 0;
}

__global__ void cnt_k(const int* __restrict__ edges) {
    int i = blockIdx.x*blockDim.x + threadIdx.x;       // over BG*EG
    int b = i >> 16;
    int e = i & (EG-1);
    int dst = edges[(size_t)b*2*EG + EG + e] & (NN-1);
    atomicAdd(&g_cnt[b*NN + dst], 1);
}

// scan + dinv + cur-zero fused: 32 blocks x 1024 (block-local exclusive scan)
__global__ void __launch_bounds__(1024) scan1_k() {
    __shared__ int warp_s[32];
    int t = threadIdx.x;
    int i = blockIdx.x*1024 + t;
    int v = g_cnt[i];
    g_dinv[i] = rsqrtf(1.0f + (float)v);               // +1 self-loop
    g_cur[i] = 0;
    int x = v;
#pragma unroll
    for (int d = 1; d < 32; d <<= 1) {
        int y = __shfl_up_sync(~0u, x, d);
        if ((t & 31) >= d) x += y;
    }
    if ((t & 31) == 31) warp_s[t >> 5] = x;
    __syncthreads();
    if (t < 32) {
        int y = warp_s[t];
#pragma unroll
        for (int d = 1; d < 32; d <<= 1) {
            int z = __shfl_up_sync(~0u, y, d);
            if (t >= d) y += z;
        }
        warp_s[t] = y;
    }
    __syncthreads();
    int wpre = (t >> 5) ? warp_s[(t >> 5) - 1] : 0;
    int incl = x + wpre;
    g_off[i] = incl - v;                                // block-local exclusive
    if (t == 1023) g_bsum[blockIdx.x] = incl;           // block total
}

// add block prefixes; each block self-sums prior block totals (no scan2 launch)
__global__ void __launch_bounds__(1024) scan3_k() {
    __shared__ int pre;
    int t = threadIdx.x, b = blockIdx.x;
    if (t < 32) {
        int v = (t < b) ? g_bsum[t] : 0;
#pragma unroll
        for (int d = 16; d > 0; d >>= 1) v += __shfl_down_sync(~0u, v, d);
        if (t == 0) pre = v;
    }
    __syncthreads();
    int i = b*1024 + t;
    g_off[i] += pre;
    if (b == 31 && t == 0) g_off[MTOT] = pre + g_bsum[31];
}

__global__ void fill_k(const int* __restrict__ edges) {
    int i = blockIdx.x*blockDim.x + threadIdx.x;       // over BG*EG
    int b = i >> 16;
    int e = i & (EG-1);
    const int* eb = edges + (size_t)b*2*EG;
    int src = eb[e]      & (NN-1);
    int dst = eb[EG + e] & (NN-1);
    int n = b*NN + dst;
    int p = atomicAdd(&g_cur[n], 1);
    g_csrc[g_off[n] + p] = src;
}

// ---------------- gather aggregation: one warp per node, no atomics ----------------
template<int F>
__device__ __forceinline__ void gather_body(const float* __restrict__ X, float* __restrict__ agg) {
    int node = blockIdx.x*8 + (threadIdx.x >> 5);      // global node id [0, MTOT)
    int lane = threadIdx.x & 31;
    int bbase = node & ~(NN-1);                        // first node of this graph
    float di = g_dinv[node];
    const float* xr = X + (size_t)node*F;
    float di2 = di*di;

    float4 a0 = *(const float4*)(xr + lane*4);
    a0.x *= di2; a0.y *= di2; a0.z *= di2; a0.w *= di2;
    float4 a1;
    if (F == 256) {
        a1 = *(const float4*)(xr + 128 + lane*4);
        a1.x *= di2; a1.y *= di2; a1.z *= di2; a1.w *= di2;
    }

    int beg = g_off[node], end = g_off[node+1];
    for (int j = beg; j < end; j++) {
        int srow = bbase + g_csrc[j];
        float nrm = g_dinv[srow] * di;
        const float* sr = X + (size_t)srow*F;
        float4 v = *(const float4*)(sr + lane*4);
        a0.x += v.x*nrm; a0.y += v.y*nrm; a0.z += v.z*nrm; a0.w += v.w*nrm;
        if (F == 256) {
            float4 w = *(const float4*)(sr + 128 + lane*4);
            a1.x += w.x*nrm; a1.y += w.y*nrm; a1.z += w.z*nrm; a1.w += w.w*nrm;
        }
    }
    float* ar = agg + (size_t)node*F;
    *(float4*)(ar + lane*4) = a0;
    if (F == 256) *(float4*)(ar + 128 + lane*4) = a1;
}

__global__ void gather1_k(const float* __restrict__ nodes) { gather_body<F0>(nodes, g_agg1); }
__global__ void gather2_k()                                { gather_body<F1>(g_h1,  g_agg2); }

// ---------------- tf32 tensor GEMM, 2-stage pipelined ----------------
// FUSE=0: C = relu(A@B + bias) -> C.
// FUSE=1: head fused: per-CTA k-partial of relu(A@B+bias) @ Wc -> g_hp[blockIdx.x]; C unused.
// Shared pool layout: mainloop As(20480B)+Bs(17408B); epilogue Cs(33792B)+Wcs(12288B).
template<int N, int K, int FUSE>
__device__ __forceinline__ void mma_gemm_body(const float* __restrict__ A,
                                              const float* __restrict__ Bm,
                                              const float* __restrict__ bias,
                                              float* __restrict__ C) {
    __shared__ __align__(16) char pool[46080];
    uint32_t* Asp = (uint32_t*)pool;                 // [2][128][20]
    uint32_t* Bsp = (uint32_t*)(pool + 20480);       // [2][16][136]
    float*    Csp = (float*)pool;                    // [64][132] f32 slab band
    float*    Wcs = (float*)(pool + 33792);          // [128][24] f32

    const int tid  = threadIdx.x;
    const int warp = tid >> 5, lane = tid & 31;
    const int wm = warp & 1, wn = warp >> 1;
    const int gid = lane >> 2, tig = lane & 3;
    const int bM = blockIdx.y * 128;
    const int bN = blockIdx.x * 128;

    float acc[4][4][4];
#pragma unroll
    for (int i = 0; i < 4; i++)
#pragma unroll
        for (int j = 0; j < 4; j++)
#pragma unroll
            for (int q = 0; q < 4; q++) acc[i][j][q] = 0.f;

    // preload k-block 0 into stage 0
#pragma unroll
    for (int j = 0; j < 2; j++) {
        int idx = tid + j*256;
        int row = idx >> 2, c4 = (idx & 3)*4;
        float4 v = *(const float4*)(A + (size_t)(bM+row)*K + c4);
        Asp[row*20 + c4+0] = f2tf32(v.x); Asp[row*20 + c4+1] = f2tf32(v.y);
        Asp[row*20 + c4+2] = f2tf32(v.z); Asp[row*20 + c4+3] = f2tf32(v.w);
        int kr = idx >> 5, c42 = (idx & 31)*4;
        float4 w = *(const float4*)(Bm + (size_t)kr*N + bN + c42);
        Bsp[kr*136 + c42+0] = f2tf32(w.x); Bsp[kr*136 + c42+1] = f2tf32(w.y);
        Bsp[kr*136 + c42+2] = f2tf32(w.z); Bsp[kr*136 + c42+3] = f2tf32(w.w);
    }
    __syncthreads();

    constexpr int NIT = K/16;
    float4 va[2], vb[2];
    for (int it = 0; it < NIT; it++) {
        const int cur = it & 1, nxt = cur ^ 1;
        uint32_t* Ac = Asp + cur*2560;
        uint32_t* Bc = Bsp + cur*2176;
        if (it + 1 < NIT) {
            const int kb = (it+1)*16;
#pragma unroll
            for (int j = 0; j < 2; j++) {
                int idx = tid + j*256;
                int row = idx >> 2, c4 = (idx & 3)*4;
                va[j] = *(const float4*)(A + (size_t)(bM+row)*K + kb + c4);
                int kr = idx >> 5, c42 = (idx & 31)*4;
                vb[j] = *(const float4*)(Bm + (size_t)(kb+kr)*N + bN + c42);
            }
        }
#pragma unroll
        for (int k8 = 0; k8 < 2; k8++) {
            const int kc = k8*8 + tig;
            uint32_t a[4][4], b[4][2];
#pragma unroll
            for (int mj = 0; mj < 4; mj++) {
                int r = wm*64 + mj*16 + gid;
                a[mj][0] = Ac[r*20 + kc];
                a[mj][1] = Ac[(r+8)*20 + kc];
                a[mj][2] = Ac[r*20 + kc+4];
                a[mj][3] = Ac[(r+8)*20 + kc+4];
            }
#pragma unroll
            for (int nj = 0; nj < 4; nj++) {
                int cN = wn*32 + nj*8 + gid;
                b[nj][0] = Bc[kc*136 + cN];
                b[nj][1] = Bc[(kc+4)*136 + cN];
            }
#pragma unroll
            for (int mj = 0; mj < 4; mj++)
#pragma unroll
                for (int nj = 0; nj < 4; nj++)
                    mma_tf32(acc[mj][nj], a[mj], b[nj]);
        }
        if (it + 1 < NIT) {
            uint32_t* An = Asp + nxt*2560;
            uint32_t* Bn = Bsp + nxt*2176;
#pragma unroll
            for (int j = 0; j < 2; j++) {
                int idx = tid + j*256;
                int row = idx >> 2, c4 = (idx & 3)*4;
                An[row*20 + c4+0] = f2tf32(va[j].x); An[row*20 + c4+1] = f2tf32(va[j].y);
                An[row*20 + c4+2] = f2tf32(va[j].z); An[row*20 + c4+3] = f2tf32(va[j].w);
                int kr = idx >> 5, c42 = (idx & 31)*4;
                Bn[kr*136 + c42+0] = f2tf32(vb[j].x); Bn[kr*136 + c42+1] = f2tf32(vb[j].y);
                Bn[kr*136 + c42+2] = f2tf32(vb[j].z); Bn[kr*136 + c42+3] = f2tf32(vb[j].w);
            }
        }
        __syncthreads();
    }

    if (FUSE == 0) {
#pragma unroll
        for (int mj = 0; mj < 4; mj++) {
            int row0 = bM + wm*64 + mj*16 + gid;
#pragma unroll
            for (int nj = 0; nj < 4; nj++) {
                int col = bN + wn*32 + nj*8 + 2*tig;
                float bx = bias[col], by = bias[col+1];
                float2 v0 = { fmaxf(acc[mj][nj][0] + bx, 0.f), fmaxf(acc[mj][nj][1] + by, 0.f) };
                float2 v1 = { fmaxf(acc[mj][nj][2] + bx, 0.f), fmaxf(acc[mj][nj][3] + by, 0.f) };
                *(float2*)(C + (size_t)row0*N + col)     = v0;
                *(float2*)(C + (size_t)(row0+8)*N + col) = v1;
            }
        }
    } else {
        // ---- fused head: relu slab (f32) -> Cs band, 3xTF32 MMA vs Wc slice -> g_hp ----
        // load Wc f32 slice [bN..bN+128) x 24 : 3072 floats
        for (int i = tid; i < 128*NHEAD/4; i += 256) {
            int kr = i / 6, c4 = (i % 6)*4;
            *(float4*)(&Wcs[kr*NHEAD + c4]) = *(const float4*)(g_Wc + (size_t)(bN+kr)*NHEAD + c4);
        }
        float* hp = g_hp + (size_t)blockIdx.x*MTOT*NHEAD;
#pragma unroll
        for (int ph = 0; ph < 2; ph++) {
            __syncthreads();
            if (wm == ph) {
#pragma unroll
                for (int mj = 0; mj < 4; mj++) {
                    int r = mj*16 + gid;
#pragma unroll
                    for (int nj = 0; nj < 4; nj++) {
                        int col = wn*32 + nj*8 + 2*tig;
                        float bx = bias[bN+col], by = bias[bN+col+1];
                        Csp[r*132 + col]       = fmaxf(acc[mj][nj][0] + bx, 0.f);
                        Csp[r*132 + col+1]     = fmaxf(acc[mj][nj][1] + by, 0.f);
                        Csp[(r+8)*132 + col]   = fmaxf(acc[mj][nj][2] + bx, 0.f);
                        Csp[(r+8)*132 + col+1] = fmaxf(acc[mj][nj][3] + by, 0.f);
                    }
                }
            }
            __syncthreads();
            if (warp < 4) {   // warp w handles m16 tile mj=w of the 64-row band
                float acch[3][4];
#pragma unroll
                for (int nj = 0; nj < 3; nj++)
#pragma unroll
                    for (int q = 0; q < 4; q++) acch[nj][q] = 0.f;
#pragma unroll
                for (int k8 = 0; k8 < 16; k8++) {
                    const int kc = k8*8 + tig;
                    int r = warp*16 + gid;
                    float af0 = Csp[r*132 + kc],   af1 = Csp[(r+8)*132 + kc];
                    float af2 = Csp[r*132 + kc+4], af3 = Csp[(r+8)*132 + kc+4];
                    uint32_t ah[4] = { f2tf32(af0), f2tf32(af1), f2tf32(af2), f2tf32(af3) };
                    uint32_t al[4] = { f2tf32(af0 - __uint_as_float(ah[0])),
                                       f2tf32(af1 - __uint_as_float(ah[1])),
                                       f2tf32(af2 - __uint_as_float(ah[2])),
                                       f2tf32(af3 - __uint_as_float(ah[3])) };
#pragma unroll
                    for (int nj = 0; nj < 3; nj++) {
                        int cN = nj*8 + gid;
                        float bf0 = Wcs[kc*NHEAD + cN], bf1 = Wcs[(kc+4)*NHEAD + cN];
                        uint32_t bh[2] = { f2tf32(bf0), f2tf32(bf1) };
                        uint32_t bl[2] = { f2tf32(bf0 - __uint_as_float(bh[0])),
                                           f2tf32(bf1 - __uint_as_float(bh[1])) };
                        mma_tf32(acch[nj], ah, bh);
                        mma_tf32(acch[nj], al, bh);
                        mma_tf32(acch[nj], ah, bl);
                    }
                }
                int row0 = bM + ph*64 + warp*16 + gid;
#pragma unroll
                for (int nj = 0; nj < 3; nj++) {
                    int col = nj*8 + 2*tig;
                    *(float2*)(hp + (size_t)row0*NHEAD + col)     = make_float2(acch[nj][0], acch[nj][1]);
                    *(float2*)(hp + (size_t)(row0+8)*NHEAD + col) = make_float2(acch[nj][2], acch[nj][3]);
                }
            }
        }
    }
}

__global__ void __launch_bounds__(256) gemm1_k(const float* __restrict__ W0,
                                               const float* __restrict__ b0) {
    mma_gemm_body<F1, F0, 0>(g_agg1, W0, b0, g_h1);
}
__global__ void __launch_bounds__(256) gemm2_k(const float* __restrict__ W1,
                                               const float* __restrict__ b1) {
    mma_gemm_body<F2, F1, 1>(g_agg2, W1, b1, nullptr);
}

// ---------------- reduce head partials: out = sum_nb hp[nb] + bc ----------------
__global__ void reduce_k(float* __restrict__ logits, float* __restrict__ values) {
    int idx = blockIdx.x*blockDim.x + threadIdx.x;     // over MTOT*NHEAD
    int row = idx / NHEAD, j = idx % NHEAD;
    float s = g_bc[j];
#pragma unroll
    for (int nb = 0; nb < 8; nb++)
        s += g_hp[(size_t)nb*MTOT*NHEAD + idx];
    if (j < NOUTD)       logits[(size_t)row*NOUTD + j] = s;
    else if (j == NOUTD) values[row] = s;
}

// ---------------- pack W_logit + W_val into [K,24] padded matrix ----------------
__global__ void pack_k(const float* __restrict__ Wl, const float* __restrict__ bl,
                       const float* __restrict__ Wv, const float* __restrict__ bv) {
    int t = blockIdx.x*blockDim.x + threadIdx.x;   // F2*NHEAD
    int k = t / NHEAD, j = t % NHEAD;
    float v = 0.f;
    if (j < NOUTD)       v = Wl[k*NOUTD + j];
    else if (j == NOUTD) v = Wv[k];
    g_Wc[t] = v;
    if (t < NHEAD) {
        float b = 0.f;
        if (t < NOUTD)       b = bl[t];
        else if (t == NOUTD) b = bv[0];
        g_bc[t] = b;
    }
}

// ---------------- launch ----------------
extern "C" void kernel_launch(void* const* d_in, const int* in_sizes, int n_in,
                              void* d_out, int out_size) {
    int iNodes, iEdges, iW0, ib0, iW1, ib1, iWl, ibl, iWv, ibv;
    if (n_in >= 10 && in_sizes[0] == BG*NN*F0) {          // insertion order
        iNodes=0; iEdges=1; iW0=2; ib0=3; iW1=4; ib1=5; iWl=6; ibl=7; iWv=8; ibv=9;
    } else {                                               // sorted-key order
        iW0=0; iW1=1; iWl=2; iWv=3; ib0=4; ib1=5; ibl=6; ibv=7; iEdges=8; iNodes=9;
    }
    const float* nodes = (const float*)d_in[iNodes];
    const int*   edges = (const int*)  d_in[iEdges];
    const float* W0 = (const float*)d_in[iW0];
    const float* b0 = (const float*)d_in[ib0];
    const float* W1 = (const float*)d_in[iW1];
    const float* b1 = (const float*)d_in[ib1];
    const float* Wl = (const float*)d_in[iWl];
    const float* bl = (const float*)d_in[ibl];
    const float* Wv = (const float*)d_in[iWv];
    const float* bv = (const float*)d_in[ibv];
    float* outp   = (float*)d_out;
    float* logits = outp;
    float* values = outp + (size_t)MTOT*NOUTD;

    // CSR build + normalization
    zero_k <<<MTOT/256, 256>>>();
    cnt_k  <<<BG*EG/256, 256>>>(edges);
    scan1_k<<<32, 1024>>>();
    scan3_k<<<32, 1024>>>();
    fill_k <<<BG*EG/256, 256>>>(edges);

    // weights pack (independent; early for overlap headroom)
    pack_k<<<F2*NHEAD/256, 256>>>(Wl, bl, Wv, bv);

    // layer 1: gather-aggregate X (128-d) then tf32 GEMM -> relu
    gather1_k<<<MTOT/8, 256>>>(nodes);
    gemm1_k  <<<dim3(F1/128, MTOT/128), 256>>>(W0, b0);

    // layer 2: gather-aggregate h1 (256-d) then tf32 GEMM with fused head partials
    gather2_k<<<MTOT/8, 256>>>();
    gemm2_k  <<<dim3(F2/128, MTOT/128), 256>>>(W1, b1);

    // reduce head partials -> logits/values
    reduce_k<<<MTOT*NHEAD/256, 256>>>(logits, values);
}

// round 15
// speedup vs baseline: 3.6459x; 1.0617x over previous
#include <cuda_runtime.h>
#include <cstdint>

#define BG 4
#define NN 8192
#define EG 65536
#define F0 128
#define F1 256
#define F2 1024
#define NOUTD 18
#define NHEAD 24
#define MTOT (BG*NN)   // 32768 rows total across graphs

// ---------------- scratch (static device globals; ONLY referenced from device code) ----------------
__device__ __align__(16) float    g_dinv[MTOT];
__device__ __align__(16) uint32_t g_agg1[(size_t)MTOT*F0];    // tf32 bits
__device__ __align__(16) float    g_h1  [(size_t)MTOT*F1];
__device__ __align__(16) uint32_t g_agg2[(size_t)MTOT*F1];    // tf32 bits
__device__ __align__(16) uint32_t g_w0t [F0*F1];              // tf32 W0
__device__ __align__(16) uint32_t g_w1t [F1*F2];              // tf32 W1
__device__ __align__(16) float    g_Wc  [F2*NHEAD];
__device__ __align__(16) float    g_bc  [NHEAD];
__device__ __align__(16) float    g_hp  [8*(size_t)MTOT*NHEAD];   // head k-partials
// CSR scratch
__device__ int g_cnt [MTOT];
__device__ int g_cur [MTOT];
__device__ int g_off [MTOT+1];
__device__ int g_bsum[32];
__device__ int g_csrc[BG*EG];

// ---------------- small helpers ----------------
__device__ __forceinline__ uint32_t f2tf32(float x) {
    uint32_t r;
    asm("cvt.rn.tf32.f32 %0, %1;" : "=r"(r) : "f"(x));
    return r;
}
__device__ __forceinline__ void mma_tf32(float c[4], const uint32_t a[4], const uint32_t b[2]) {
    asm("mma.sync.aligned.m16n8k8.row.col.f32.tf32.tf32.f32 "
        "{%0,%1,%2,%3}, {%4,%5,%6,%7}, {%8,%9}, {%0,%1,%2,%3};"
        : "+f"(c[0]), "+f"(c[1]), "+f"(c[2]), "+f"(c[3])
        : "r"(a[0]), "r"(a[1]), "r"(a[2]), "r"(a[3]), "r"(b[0]), "r"(b[1]));
}
__device__ __forceinline__ uint32_t smem_u32(const void* p) {
    uint32_t a;
    asm("{ .reg .u64 t; cvta.to.shared.u64 t, %1; cvt.u32.u64 %0, t; }" : "=r"(a) : "l"(p));
    return a;
}
__device__ __forceinline__ void cp16(uint32_t s, const void* g) {
    asm volatile("cp.async.cg.shared.global [%0], [%1], 16;" :: "r"(s), "l"(g));
}
__device__ __forceinline__ void cp_commit() { asm volatile("cp.async.commit_group;"); }
template<int N> __device__ __forceinline__ void cp_wait() {
    asm volatile("cp.async.wait_group %0;" :: "n"(N));
}

// ---------------- prep: zero cnt, pack Wc/bc, convert W0/W1 to tf32 ----------------
__global__ void prep_k(const float* __restrict__ W0, const float* __restrict__ W1,
                       const float* __restrict__ Wl, const float* __restrict__ bl,
                       const float* __restrict__ Wv, const float* __restrict__ bv) {
    int i = blockIdx.x*blockDim.x + threadIdx.x;       // over F1*F2 = 262144
    g_w1t[i] = f2tf32(W1[i]);
    if (i < F0*F1) g_w0t[i] = f2tf32(W0[i]);
    if (i < MTOT)  g_cnt[i] = 0;
    if (i < F2*NHEAD) {
        int k = i / NHEAD, j = i % NHEAD;
        float v = 0.f;
        if (j < NOUTD)       v = Wl[k*NOUTD + j];
        else if (j == NOUTD) v = Wv[k];
        g_Wc[i] = v;
    }
    if (i < NHEAD) {
        float b = 0.f;
        if (i < NOUTD)       b = bl[i];
        else if (i == NOUTD) b = bv[0];
        g_bc[i] = b;
    }
}

// ---------------- CSR build ----------------
__global__ void cnt_k(const int* __restrict__ edges) {
    int i = blockIdx.x*blockDim.x + threadIdx.x;       // over BG*EG
    int b = i >> 16;
    int e = i & (EG-1);
    int dst = edges[(size_t)b*2*EG + EG + e] & (NN-1);
    atomicAdd(&g_cnt[b*NN + dst], 1);
}

// scan + dinv + cur-zero fused: 32 blocks x 1024 (block-local exclusive scan)
__global__ void __launch_bounds__(1024) scan1_k() {
    __shared__ int warp_s[32];
    int t = threadIdx.x;
    int i = blockIdx.x*1024 + t;
    int v = g_cnt[i];
    g_dinv[i] = rsqrtf(1.0f + (float)v);               // +1 self-loop
    g_cur[i] = 0;
    int x = v;
#pragma unroll
    for (int d = 1; d < 32; d <<= 1) {
        int y = __shfl_up_sync(~0u, x, d);
        if ((t & 31) >= d) x += y;
    }
    if ((t & 31) == 31) warp_s[t >> 5] = x;
    __syncthreads();
    if (t < 32) {
        int y = warp_s[t];
#pragma unroll
        for (int d = 1; d < 32; d <<= 1) {
            int z = __shfl_up_sync(~0u, y, d);
            if (t >= d) y += z;
        }
        warp_s[t] = y;
    }
    __syncthreads();
    int wpre = (t >> 5) ? warp_s[(t >> 5) - 1] : 0;
    int incl = x + wpre;
    g_off[i] = incl - v;                                // block-local exclusive
    if (t == 1023) g_bsum[blockIdx.x] = incl;           // block total
}

// add block prefixes; each block self-sums prior block totals
__global__ void __launch_bounds__(1024) scan3_k() {
    __shared__ int pre;
    int t = threadIdx.x, b = blockIdx.x;
    if (t < 32) {
        int v = (t < b) ? g_bsum[t] : 0;
#pragma unroll
        for (int d = 16; d > 0; d >>= 1) v += __shfl_down_sync(~0u, v, d);
        if (t == 0) pre = v;
    }
    __syncthreads();
    int i = b*1024 + t;
    g_off[i] += pre;
    if (b == 31 && t == 0) g_off[MTOT] = pre + g_bsum[31];
}

__global__ void fill_k(const int* __restrict__ edges) {
    int i = blockIdx.x*blockDim.x + threadIdx.x;       // over BG*EG
    int b = i >> 16;
    int e = i & (EG-1);
    const int* eb = edges + (size_t)b*2*EG;
    int src = eb[e]      & (NN-1);
    int dst = eb[EG + e] & (NN-1);
    int n = b*NN + dst;
    int p = atomicAdd(&g_cur[n], 1);
    g_csrc[g_off[n] + p] = src;
}

// ---------------- gather aggregation (writes tf32): one warp per node ----------------
template<int F>
__device__ __forceinline__ void gather_body(const float* __restrict__ X, uint32_t* __restrict__ agg) {
    int node = blockIdx.x*8 + (threadIdx.x >> 5);      // global node id [0, MTOT)
    int lane = threadIdx.x & 31;
    int bbase = node & ~(NN-1);                        // first node of this graph
    float di = g_dinv[node];
    const float* xr = X + (size_t)node*F;
    float di2 = di*di;

    float4 a0 = *(const float4*)(xr + lane*4);
    a0.x *= di2; a0.y *= di2; a0.z *= di2; a0.w *= di2;
    float4 a1;
    if (F == 256) {
        a1 = *(const float4*)(xr + 128 + lane*4);
        a1.x *= di2; a1.y *= di2; a1.z *= di2; a1.w *= di2;
    }

    int beg = g_off[node], end = g_off[node+1];
    for (int j = beg; j < end; j++) {
        int srow = bbase + g_csrc[j];
        float nrm = g_dinv[srow] * di;
        const float* sr = X + (size_t)srow*F;
        float4 v = *(const float4*)(sr + lane*4);
        a0.x += v.x*nrm; a0.y += v.y*nrm; a0.z += v.z*nrm; a0.w += v.w*nrm;
        if (F == 256) {
            float4 w = *(const float4*)(sr + 128 + lane*4);
            a1.x += w.x*nrm; a1.y += w.y*nrm; a1.z += w.z*nrm; a1.w += w.w*nrm;
        }
    }
    uint32_t* ar = agg + (size_t)node*F;
    uint4 u0 = { f2tf32(a0.x), f2tf32(a0.y), f2tf32(a0.z), f2tf32(a0.w) };
    *(uint4*)(ar + lane*4) = u0;
    if (F == 256) {
        uint4 u1 = { f2tf32(a1.x), f2tf32(a1.y), f2tf32(a1.z), f2tf32(a1.w) };
        *(uint4*)(ar + 128 + lane*4) = u1;
    }
}

__global__ void gather1_k(const float* __restrict__ nodes) { gather_body<F0>(nodes, g_agg1); }
__global__ void gather2_k()                                { gather_body<F1>(g_h1,  g_agg2); }

// ---------------- tf32 GEMM, 3-stage cp.async pipeline ----------------
// A,B pre-converted tf32. FUSE=0: C=relu(A@B+bias). FUSE=1: fused head partial -> g_hp.
// Dyn smem: A stages [3][128][20]w at 0 (30720B), B stages [3][16][136]w at 30720 (26112B) = 56832B.
// FUSE epilogue reuses pool: Csp [64][132]f at 0 (33792B), Wcs [128][24]f at 33792 (12288B).
#define SMEM_GEMM 56832

template<int N, int K, int FUSE>
__device__ __forceinline__ void mma_gemm_body(const uint32_t* __restrict__ A,
                                              const uint32_t* __restrict__ Bm,
                                              const float* __restrict__ bias,
                                              float* __restrict__ C) {
    extern __shared__ __align__(16) char pool[];
    uint32_t* Aw = (uint32_t*)pool;                  // stage s -> +s*2560 words
    uint32_t* Bw = (uint32_t*)(pool + 30720);        // stage s -> +s*2176 words
    float*    Csp = (float*)pool;
    float*    Wcs = (float*)(pool + 33792);
    const uint32_t sA = smem_u32(pool);
    const uint32_t sB = sA + 30720;

    const int tid  = threadIdx.x;
    const int warp = tid >> 5, lane = tid & 31;
    const int wm = warp & 1, wn = warp >> 1;
    const int gid = lane >> 2, tig = lane & 3;
    const int bM = blockIdx.y * 128;
    const int bN = blockIdx.x * 128;

    // per-thread copy slots
    const int arow0 = tid >> 2,        ac0 = (tid & 3)*4;          // A: idx=tid
    const int arow1 = (tid+256) >> 2,  ac1 = ((tid+256) & 3)*4;    // A: idx=tid+256
    const int bkr0  = tid >> 5,        bc0 = (tid & 31)*4;
    const int bkr1  = (tid+256) >> 5,  bc1 = ((tid+256) & 31)*4;

    float acc[4][4][4];
#pragma unroll
    for (int i = 0; i < 4; i++)
#pragma unroll
        for (int j = 0; j < 4; j++)
#pragma unroll
            for (int q = 0; q < 4; q++) acc[i][j][q] = 0.f;

    auto issue = [&](int s, int kb) {
        uint32_t a_s = sA + s*10240, b_s = sB + s*8704;
        cp16(a_s + arow0*80 + ac0*4, A + (size_t)(bM+arow0)*K + kb + ac0);
        cp16(a_s + arow1*80 + ac1*4, A + (size_t)(bM+arow1)*K + kb + ac1);
        cp16(b_s + bkr0*544 + bc0*4, Bm + (size_t)(kb+bkr0)*N + bN + bc0);
        cp16(b_s + bkr1*544 + bc1*4, Bm + (size_t)(kb+bkr1)*N + bN + bc1);
        cp_commit();
    };

    constexpr int NIT = K/16;
    issue(0, 0);
    issue(1, 16);

    for (int it = 0; it < NIT; it++) {
        const int cur = it % 3;
        if (it == NIT-1) cp_wait<0>(); else cp_wait<1>();
        __syncthreads();
        const uint32_t* Ac = Aw + cur*2560;
        const uint32_t* Bc = Bw + cur*2176;
#pragma unroll
        for (int k8 = 0; k8 < 2; k8++) {
            const int kc = k8*8 + tig;
            uint32_t a[4][4], b[4][2];
#pragma unroll
            for (int mj = 0; mj < 4; mj++) {
                int r = wm*64 + mj*16 + gid;
                a[mj][0] = Ac[r*20 + kc];
                a[mj][1] = Ac[(r+8)*20 + kc];
                a[mj][2] = Ac[r*20 + kc+4];
                a[mj][3] = Ac[(r+8)*20 + kc+4];
            }
#pragma unroll
            for (int nj = 0; nj < 4; nj++) {
                int cN = wn*32 + nj*8 + gid;
                b[nj][0] = Bc[kc*136 + cN];
                b[nj][1] = Bc[(kc+4)*136 + cN];
            }
#pragma unroll
            for (int mj = 0; mj < 4; mj++)
#pragma unroll
                for (int nj = 0; nj < 4; nj++)
                    mma_tf32(acc[mj][nj], a[mj], b[nj]);
        }
        if (it + 2 < NIT) issue((it+2) % 3, (it+2)*16);
    }

    if (FUSE == 0) {
#pragma unroll
        for (int mj = 0; mj < 4; mj++) {
            int row0 = bM + wm*64 + mj*16 + gid;
#pragma unroll
            for (int nj = 0; nj < 4; nj++) {
                int col = bN + wn*32 + nj*8 + 2*tig;
                float bx = bias[col], by = bias[col+1];
                float2 v0 = { fmaxf(acc[mj][nj][0] + bx, 0.f), fmaxf(acc[mj][nj][1] + by, 0.f) };
                float2 v1 = { fmaxf(acc[mj][nj][2] + bx, 0.f), fmaxf(acc[mj][nj][3] + by, 0.f) };
                *(float2*)(C + (size_t)row0*N + col)     = v0;
                *(float2*)(C + (size_t)(row0+8)*N + col) = v1;
            }
        }
    } else {
        __syncthreads();   // all MMA smem reads done before pool reuse
        for (int i = tid; i < 128*NHEAD/4; i += 256) {
            int kr = i / 6, c4 = (i % 6)*4;
            *(float4*)(&Wcs[kr*NHEAD + c4]) = *(const float4*)(g_Wc + (size_t)(bN+kr)*NHEAD + c4);
        }
        float* hp = g_hp + (size_t)blockIdx.x*MTOT*NHEAD;
#pragma unroll
        for (int ph = 0; ph < 2; ph++) {
            __syncthreads();
            if (wm == ph) {
#pragma unroll
                for (int mj = 0; mj < 4; mj++) {
                    int r = mj*16 + gid;
#pragma unroll
                    for (int nj = 0; nj < 4; nj++) {
                        int col = wn*32 + nj*8 + 2*tig;
                        float bx = bias[bN+col], by = bias[bN+col+1];
                        Csp[r*132 + col]       = fmaxf(acc[mj][nj][0] + bx, 0.f);
                        Csp[r*132 + col+1]     = fmaxf(acc[mj][nj][1] + by, 0.f);
                        Csp[(r+8)*132 + col]   = fmaxf(acc[mj][nj][2] + bx, 0.f);
                        Csp[(r+8)*132 + col+1] = fmaxf(acc[mj][nj][3] + by, 0.f);
                    }
                }
            }
            __syncthreads();
            if (warp < 4) {
                float acch[3][4];
#pragma unroll
                for (int nj = 0; nj < 3; nj++)
#pragma unroll
                    for (int q = 0; q < 4; q++) acch[nj][q] = 0.f;
#pragma unroll
                for (int k8 = 0; k8 < 16; k8++) {
                    const int kc = k8*8 + tig;
                    int r = warp*16 + gid;
                    float af0 = Csp[r*132 + kc],   af1 = Csp[(r+8)*132 + kc];
                    float af2 = Csp[r*132 + kc+4], af3 = Csp[(r+8)*132 + kc+4];
                    uint32_t ah[4] = { f2tf32(af0), f2tf32(af1), f2tf32(af2), f2tf32(af3) };
                    uint32_t al[4] = { f2tf32(af0 - __uint_as_float(ah[0])),
                                       f2tf32(af1 - __uint_as_float(ah[1])),
                                       f2tf32(af2 - __uint_as_float(ah[2])),
                                       f2tf32(af3 - __uint_as_float(ah[3])) };
#pragma unroll
                    for (int nj = 0; nj < 3; nj++) {
                        int cN = nj*8 + gid;
                        float bf0 = Wcs[kc*NHEAD + cN], bf1 = Wcs[(kc+4)*NHEAD + cN];
                        uint32_t bh[2] = { f2tf32(bf0), f2tf32(bf1) };
                        uint32_t bl[2] = { f2tf32(bf0 - __uint_as_float(bh[0])),
                                           f2tf32(bf1 - __uint_as_float(bh[1])) };
                        mma_tf32(acch[nj], ah, bh);
                        mma_tf32(acch[nj], al, bh);
                        mma_tf32(acch[nj], ah, bl);
                    }
                }
                int row0 = bM + ph*64 + warp*16 + gid;
#pragma unroll
                for (int nj = 0; nj < 3; nj++) {
                    int col = nj*8 + 2*tig;
                    *(float2*)(hp + (size_t)row0*NHEAD + col)     = make_float2(acch[nj][0], acch[nj][1]);
                    *(float2*)(hp + (size_t)(row0+8)*NHEAD + col) = make_float2(acch[nj][2], acch[nj][3]);
                }
            }
        }
    }
}

__global__ void __launch_bounds__(256) gemm1_k(const float* __restrict__ b0) {
    mma_gemm_body<F1, F0, 0>(g_agg1, g_w0t, b0, g_h1);
}
__global__ void __launch_bounds__(256) gemm2_k(const float* __restrict__ b1) {
    mma_gemm_body<F2, F1, 1>(g_agg2, g_w1t, b1, nullptr);
}

// ---------------- reduce head partials: out = sum_nb hp[nb] + bc ----------------
__global__ void reduce_k(float* __restrict__ logits, float* __restrict__ values) {
    int idx = blockIdx.x*blockDim.x + threadIdx.x;     // over MTOT*NHEAD
    int row = idx / NHEAD, j = idx % NHEAD;
    float s = g_bc[j];
#pragma unroll
    for (int nb = 0; nb < 8; nb++)
        s += g_hp[(size_t)nb*MTOT*NHEAD + idx];
    if (j < NOUTD)       logits[(size_t)row*NOUTD + j] = s;
    else if (j == NOUTD) values[row] = s;
}

// ---------------- launch ----------------
extern "C" void kernel_launch(void* const* d_in, const int* in_sizes, int n_in,
                              void* d_out, int out_size) {
    int iNodes, iEdges, iW0, ib0, iW1, ib1, iWl, ibl, iWv, ibv;
    if (n_in >= 10 && in_sizes[0] == BG*NN*F0) {          // insertion order
        iNodes=0; iEdges=1; iW0=2; ib0=3; iW1=4; ib1=5; iWl=6; ibl=7; iWv=8; ibv=9;
    } else {                                               // sorted-key order
        iW0=0; iW1=1; iWl=2; iWv=3; ib0=4; ib1=5; ibl=6; ibv=7; iEdges=8; iNodes=9;
    }
    const float* nodes = (const float*)d_in[iNodes];
    const int*   edges = (const int*)  d_in[iEdges];
    const float* W0 = (const float*)d_in[iW0];
    const float* b0 = (const float*)d_in[ib0];
    const float* W1 = (const float*)d_in[iW1];
    const float* b1 = (const float*)d_in[ib1];
    const float* Wl = (const float*)d_in[iWl];
    const float* bl = (const float*)d_in[ibl];
    const float* Wv = (const float*)d_in[iWv];
    const float* bv = (const float*)d_in[ibv];
    float* outp   = (float*)d_out;
    float* logits = outp;
    float* values = outp + (size_t)MTOT*NOUTD;

    static_assert(SMEM_GEMM <= 227*1024, "smem");
    cudaFuncSetAttribute(gemm1_k, cudaFuncAttributeMaxDynamicSharedMemorySize, SMEM_GEMM);
    cudaFuncSetAttribute(gemm2_k, cudaFuncAttributeMaxDynamicSharedMemorySize, SMEM_GEMM);

    // prep (cnt zero + Wc/bc pack + W0/W1 tf32 convert) and CSR build
    prep_k <<<F1*F2/256, 256>>>(W0, W1, Wl, bl, Wv, bv);
    cnt_k  <<<BG*EG/256, 256>>>(edges);
    scan1_k<<<32, 1024>>>();
    scan3_k<<<32, 1024>>>();
    fill_k <<<BG*EG/256, 256>>>(edges);

    // layer 1: gather-aggregate X (128-d, tf32 out) then pipelined tf32 GEMM -> relu
    gather1_k<<<MTOT/8, 256>>>(nodes);
    gemm1_k  <<<dim3(F1/128, MTOT/128), 256, SMEM_GEMM>>>(b0);

    // layer 2: gather-aggregate h1 (256-d, tf32 out) then pipelined GEMM + fused head
    gather2_k<<<MTOT/8, 256>>>();
    gemm2_k  <<<dim3(F2/128, MTOT/128), 256, SMEM_GEMM>>>(b1);

    // reduce head partials -> logits/values
    reduce_k<<<MTOT*NHEAD/256, 256>>>(logits, values);
}